// round 11
// baseline (speedup 1.0000x reference)
#include <cuda_runtime.h>
#include <cuda_bf16.h>
#include <mma.h>
#include <math.h>
#include <stdint.h>

using namespace nvcuda;

#define BATCH 1024
#define SEQ   200
#define NLIN  400
#define HID   128
#define H2    256
#define H3    384
#define TB    16
#define BL    (BATCH * SEQ)

// ---------------- scratch (static device globals; no allocation) ----------------
__device__ float g_code[(size_t)BATCH * NLIN];
__device__ __nv_bfloat16 g_ah[(size_t)BL * H2];
__device__ __nv_bfloat16 g_al[(size_t)BL * H2];
__device__ float g_xg1 [(size_t)2 * BL * H3];
__device__ float g_h1  [(size_t)BL * H2];

__device__ __forceinline__ float sigf(float x) {
    return 1.f / (1.f + __expf(-x));
}
__device__ __forceinline__ float tanhfast(float x) {
    float e = __expf(-2.f * fabsf(x));
    float t = (1.f - e) / (1.f + e);
    return x < 0.f ? -t : t;
}

// ---------------- small SGEMM for dec_linear ----------------
__global__ __launch_bounds__(256) void sgemm_nt(
    const float* __restrict__ A, const float* __restrict__ B,
    const float* __restrict__ bias, float* __restrict__ C,
    int M, int N, int K)
{
    __shared__ float As[16][65];
    __shared__ float Bs[16][65];
    int tid = threadIdx.x;
    int tx = tid & 15, ty = tid >> 4;
    int bm0 = blockIdx.x * 64, bn0 = blockIdx.y * 64;
    int lrow = tid >> 2;
    int lc4  = (tid & 3) * 4;

    float acc[4][4] = {};

    for (int k0 = 0; k0 < K; k0 += 16) {
        float4 av = *(const float4*)(A + (size_t)(bm0 + lrow) * K + k0 + lc4);
        float4 bv = make_float4(0.f, 0.f, 0.f, 0.f);
        if (bn0 + lrow < N)
            bv = *(const float4*)(B + (size_t)(bn0 + lrow) * K + k0 + lc4);
        As[lc4 + 0][lrow] = av.x; As[lc4 + 1][lrow] = av.y;
        As[lc4 + 2][lrow] = av.z; As[lc4 + 3][lrow] = av.w;
        Bs[lc4 + 0][lrow] = bv.x; Bs[lc4 + 1][lrow] = bv.y;
        Bs[lc4 + 2][lrow] = bv.z; Bs[lc4 + 3][lrow] = bv.w;
        __syncthreads();
        #pragma unroll
        for (int kk = 0; kk < 16; ++kk) {
            float a[4], b[4];
            #pragma unroll
            for (int i = 0; i < 4; ++i) { a[i] = As[kk][ty * 4 + i]; b[i] = Bs[kk][tx * 4 + i]; }
            #pragma unroll
            for (int i = 0; i < 4; ++i)
                #pragma unroll
                for (int j = 0; j < 4; ++j)
                    acc[i][j] = fmaf(a[i], b[j], acc[i][j]);
        }
        __syncthreads();
    }

    #pragma unroll
    for (int i = 0; i < 4; ++i) {
        int row = bm0 + ty * 4 + i;
        #pragma unroll
        for (int j = 0; j < 4; ++j) {
            int col = bn0 + tx * 4 + j;
            if (col < N)
                C[(size_t)row * N + col] = acc[i][j] + bias[col];
        }
    }
}

// ---------------- layer-1 projection GEMM v3 (unchanged from R10) ----------------
#define LDW3 264
#define LDA3 72
#define LDB3 132
#define X3_BIAS 0
#define X3_WH   8448
#define X3_WL   (X3_WH  + 128 * LDW3 * 2)
#define X3_AH0  (X3_WL  + 128 * LDW3 * 2)
#define X3_AH1  (X3_AH0 + 128 * LDA3 * 2)
#define X3_AL0  (X3_AH1 + 128 * LDA3 * 2)
#define X3_AL1  (X3_AL0 + 128 * LDA3 * 2)
#define SMEM_X3 (X3_AL1 + 128 * LDA3 * 2)

__global__ __launch_bounds__(256, 1) void xgemm3(
    const __nv_bfloat16* __restrict__ Ah, const __nv_bfloat16* __restrict__ Al,
    const float* __restrict__ Bf, const float* __restrict__ Bb,
    const float* __restrict__ biasf, const float* __restrict__ biasb,
    float* __restrict__ C)
{
    extern __shared__ char smem[];
    float* sBias = (float*)(smem + X3_BIAS);
    __nv_bfloat16* sWh = (__nv_bfloat16*)(smem + X3_WH);
    __nv_bfloat16* sWl = (__nv_bfloat16*)(smem + X3_WL);
    __nv_bfloat16* sAh[2] = { (__nv_bfloat16*)(smem + X3_AH0), (__nv_bfloat16*)(smem + X3_AH1) };
    __nv_bfloat16* sAl[2] = { (__nv_bfloat16*)(smem + X3_AL0), (__nv_bfloat16*)(smem + X3_AL1) };

    const int tid = threadIdx.x;
    const int wid = tid >> 5;
    const int wm = wid & 3;
    const int wn = wid >> 2;

    const int bx = blockIdx.x;
    const int dir = bx / 3;
    const int ncol0 = (bx % 3) * 128;
    const float* W = dir ? Bb : Bf;
    const float* bias = dir ? biasb : biasf;
    float* Cb = C + (size_t)dir * BL * H3;

    for (int idx = tid; idx < 128 * 256; idx += 256) {
        int n = idx >> 8, k = idx & 255;
        float w = W[(size_t)(ncol0 + n) * H2 + k];
        __nv_bfloat16 hi = __float2bfloat16(w);
        __nv_bfloat16 lo = __float2bfloat16(w - __bfloat162float(hi));
        sWh[n * LDW3 + k] = hi;
        sWl[n * LDW3 + k] = lo;
    }
    for (int idx = tid; idx < 16 * 128; idx += 256) {
        int r = idx >> 7, c = idx & 127;
        sBias[r * LDB3 + c] = bias[ncol0 + c];
    }

    const int pr = tid >> 1;
    const int pc = (tid & 1) * 32;
    uint4 ph[4], pl[4];

    #define FETCH_CHUNK(g) do { \
        int _it = (g) >> 2, _c = (g) & 3; \
        size_t _base = (((size_t)_it * 200 + blockIdx.y) * 128 + pr) * H2 + _c * 64 + pc; \
        ph[0] = *(const uint4*)(Ah + _base);      ph[1] = *(const uint4*)(Ah + _base + 8); \
        ph[2] = *(const uint4*)(Ah + _base + 16); ph[3] = *(const uint4*)(Ah + _base + 24); \
        pl[0] = *(const uint4*)(Al + _base);      pl[1] = *(const uint4*)(Al + _base + 8); \
        pl[2] = *(const uint4*)(Al + _base + 16); pl[3] = *(const uint4*)(Al + _base + 24); \
    } while (0)

    FETCH_CHUNK(0);
    __syncthreads();

    for (int it = 0; it < 8; ++it) {
        const size_t m0 = ((size_t)it * 200 + blockIdx.y) * 128;

        wmma::fragment<wmma::accumulator, 16, 16, 16, float> acc[2][4];
        #pragma unroll
        for (int i = 0; i < 2; ++i)
            #pragma unroll
            for (int j = 0; j < 4; ++j)
                wmma::load_matrix_sync(acc[i][j], sBias + wn * 64 + j * 16, LDB3, wmma::mem_row_major);

        for (int c = 0; c < 4; ++c) {
            const int g = it * 4 + c;
            const int buf = g & 1;

            __nv_bfloat16* dH = sAh[buf] + pr * LDA3 + pc;
            __nv_bfloat16* dL = sAl[buf] + pr * LDA3 + pc;
            *(uint4*)(dH)      = ph[0]; *(uint4*)(dH + 8)  = ph[1];
            *(uint4*)(dH + 16) = ph[2]; *(uint4*)(dH + 24) = ph[3];
            *(uint4*)(dL)      = pl[0]; *(uint4*)(dL + 8)  = pl[1];
            *(uint4*)(dL + 16) = pl[2]; *(uint4*)(dL + 24) = pl[3];

            if (g + 1 < 32) FETCH_CHUNK(g + 1);
            __syncthreads();

            #pragma unroll
            for (int kk = 0; kk < 4; ++kk) {
                wmma::fragment<wmma::matrix_a, 16, 16, 16, __nv_bfloat16, wmma::row_major> fah[2], fal[2];
                wmma::fragment<wmma::matrix_b, 16, 16, 16, __nv_bfloat16, wmma::col_major> fbh[4], fbl[4];
                #pragma unroll
                for (int i = 0; i < 2; ++i) {
                    wmma::load_matrix_sync(fah[i], sAh[buf] + (wm * 32 + i * 16) * LDA3 + kk * 16, LDA3);
                    wmma::load_matrix_sync(fal[i], sAl[buf] + (wm * 32 + i * 16) * LDA3 + kk * 16, LDA3);
                }
                #pragma unroll
                for (int j = 0; j < 4; ++j) {
                    wmma::load_matrix_sync(fbh[j], sWh + (wn * 64 + j * 16) * LDW3 + c * 64 + kk * 16, LDW3);
                    wmma::load_matrix_sync(fbl[j], sWl + (wn * 64 + j * 16) * LDW3 + c * 64 + kk * 16, LDW3);
                }
                #pragma unroll
                for (int i = 0; i < 2; ++i)
                    #pragma unroll
                    for (int j = 0; j < 4; ++j) {
                        wmma::mma_sync(acc[i][j], fah[i], fbh[j], acc[i][j]);
                        wmma::mma_sync(acc[i][j], fah[i], fbl[j], acc[i][j]);
                        wmma::mma_sync(acc[i][j], fal[i], fbh[j], acc[i][j]);
                    }
            }
        }

        #pragma unroll
        for (int i = 0; i < 2; ++i)
            #pragma unroll
            for (int j = 0; j < 4; ++j)
                wmma::store_matrix_sync(
                    Cb + (m0 + wm * 32 + i * 16) * H3 + ncol0 + wn * 64 + j * 16,
                    acc[i][j], H3, wmma::mem_row_major);
    }
    #undef FETCH_CHUNK
}

// ---------------- tensor-core GRU layer (3-way split accumulators) ----------------
#define LDWP 392
#define LDH  136
#define LDEPI 196
#define GOFF_WH  0
#define GOFF_WL  (GOFF_WH + 128 * LDWP * 2)
#define GOFF_HH  (GOFF_WL + 128 * LDWP * 2)
#define GOFF_HL  (GOFF_HH + TB * LDH * 2)
#define GOFF_EPI (GOFF_HL + TB * LDH * 2)
#define GOFF_BHH (GOFF_EPI + TB * LDEPI * 4)
#define GOFF_BIH (GOFF_BHH + H3 * 4)
#define GOFF_WIH (GOFF_BIH + H3 * 4)
#define SMEM_GRUTC (GOFF_WIH + H3 * 2 * 4)

template <int LAYER>
__global__ __launch_bounds__(512, 1) void gru_tc(
    const float* __restrict__ code,
    const float* __restrict__ xg,
    const float* __restrict__ Wih_f, const float* __restrict__ Wih_b,
    const float* __restrict__ Whh_f, const float* __restrict__ Whh_b,
    const float* __restrict__ bih_f, const float* __restrict__ bih_b,
    const float* __restrict__ bhh_f, const float* __restrict__ bhh_b,
    float* __restrict__ houtF,
    __nv_bfloat16* __restrict__ houtH,
    __nv_bfloat16* __restrict__ houtL)
{
    extern __shared__ char smem[];
    __nv_bfloat16* sWh = (__nv_bfloat16*)(smem + GOFF_WH);
    __nv_bfloat16* sWl = (__nv_bfloat16*)(smem + GOFF_WL);
    __nv_bfloat16* sHh = (__nv_bfloat16*)(smem + GOFF_HH);
    __nv_bfloat16* sHl = (__nv_bfloat16*)(smem + GOFF_HL);
    float* sEpi = (float*)(smem + GOFF_EPI);
    float* sBhh = (float*)(smem + GOFF_BHH);
    float* sBih = (float*)(smem + GOFF_BIH);
    float* sWih = (float*)(smem + GOFF_WIH);

    const int tid = threadIdx.x;
    const int dir = blockIdx.y;
    const int gb0 = blockIdx.x * TB;
    const float* Whh = dir ? Whh_b : Whh_f;
    const float* bhh = dir ? bhh_b : bhh_f;

    for (int idx = tid; idx < H3 * HID; idx += 512) {
        int r = idx >> 7, j = idx & 127;
        int g = r >> 7, k = r & 127;
        int colp = (k >> 6) * 192 + 3 * (k & 63) + g;
        float w = Whh[r * HID + j];
        __nv_bfloat16 hi = __float2bfloat16(w);
        __nv_bfloat16 lo = __float2bfloat16(w - __bfloat162float(hi));
        sWh[j * LDWP + colp] = hi;
        sWl[j * LDWP + colp] = lo;
    }
    for (int idx = tid; idx < H3; idx += 512) {
        sBhh[idx] = bhh[idx];
        if (LAYER == 0) {
            const float* Wih = dir ? Wih_b : Wih_f;
            const float* bih = dir ? bih_b : bih_f;
            sBih[idx] = bih[idx];
            sWih[idx * 2 + 0] = Wih[idx * 2 + 0];
            sWih[idx * 2 + 1] = Wih[idx * 2 + 1];
        }
    }
    for (int idx = tid; idx < TB * LDH; idx += 512) {
        sHh[idx] = __float2bfloat16(0.f);
        sHl[idx] = __float2bfloat16(0.f);
    }
    __syncthreads();

    const int wid = tid >> 5, lane = tid & 31;
    const int b = wid;
    const int k0 = lane * 2;
    float h[4] = {0.f, 0.f, 0.f, 0.f};

    for (int t = 0; t < SEQ; ++t) {
        const int tt = dir ? (SEQ - 1 - t) : t;

        float xr[4], xz[4], xn[4];
        if (LAYER == 1) {
            const float* xp = xg + ((size_t)dir * BL + (size_t)(gb0 + b) * SEQ + tt) * H3;
            float2 v;
            v = *(const float2*)(xp + k0);            xr[0] = v.x; xr[1] = v.y;
            v = *(const float2*)(xp + 64 + k0);       xr[2] = v.x; xr[3] = v.y;
            v = *(const float2*)(xp + 128 + k0);      xz[0] = v.x; xz[1] = v.y;
            v = *(const float2*)(xp + 192 + k0);      xz[2] = v.x; xz[3] = v.y;
            v = *(const float2*)(xp + 256 + k0);      xn[0] = v.x; xn[1] = v.y;
            v = *(const float2*)(xp + 320 + k0);      xn[2] = v.x; xn[3] = v.y;
        } else {
            float c0 = __ldg(&code[(size_t)(gb0 + b) * NLIN + tt * 2 + 0]);
            float c1 = __ldg(&code[(size_t)(gb0 + b) * NLIN + tt * 2 + 1]);
            #pragma unroll
            for (int i = 0; i < 4; ++i) {
                int k = (i >> 1) * 64 + k0 + (i & 1);
                xr[i] = fmaf(c0, sWih[k * 2],           fmaf(c1, sWih[k * 2 + 1],           sBih[k]));
                xz[i] = fmaf(c0, sWih[(128 + k) * 2],   fmaf(c1, sWih[(128 + k) * 2 + 1],   sBih[128 + k]));
                xn[i] = fmaf(c0, sWih[(256 + k) * 2],   fmaf(c1, sWih[(256 + k) * 2 + 1],   sBih[256 + k]));
            }
        }

        // ---- mma chunk 0 (cols' 0..191): 3 independent accumulator chains ----
        if (wid < 12) {
            wmma::fragment<wmma::accumulator, 16, 16, 16, float> accA, accB, accC;
            wmma::fill_fragment(accA, 0.f);
            wmma::fill_fragment(accB, 0.f);
            wmma::fill_fragment(accC, 0.f);
            #pragma unroll
            for (int jf = 0; jf < 8; ++jf) {
                wmma::fragment<wmma::matrix_a, 16, 16, 16, __nv_bfloat16, wmma::row_major> aH, aL;
                wmma::fragment<wmma::matrix_b, 16, 16, 16, __nv_bfloat16, wmma::row_major> bH, bL;
                wmma::load_matrix_sync(aH, sHh + jf * 16, LDH);
                wmma::load_matrix_sync(aL, sHl + jf * 16, LDH);
                wmma::load_matrix_sync(bH, sWh + (jf * 16) * LDWP + wid * 16, LDWP);
                wmma::load_matrix_sync(bL, sWl + (jf * 16) * LDWP + wid * 16, LDWP);
                wmma::mma_sync(accA, aH, bH, accA);
                wmma::mma_sync(accB, aH, bL, accB);
                wmma::mma_sync(accC, aL, bH, accC);
            }
            #pragma unroll
            for (int e = 0; e < accA.num_elements; ++e)
                accA.x[e] += accB.x[e] + accC.x[e];
            wmma::store_matrix_sync(sEpi + wid * 16, accA, LDEPI, wmma::mem_row_major);
        }
        __syncthreads();

        #pragma unroll
        for (int i = 0; i < 2; ++i) {
            int k = k0 + i;
            const float* e = sEpi + b * LDEPI + 3 * k;
            float r = sigf(xr[i] + e[0] + sBhh[k]);
            float z = sigf(xz[i] + e[1] + sBhh[128 + k]);
            float n = tanhfast(xn[i] + r * (e[2] + sBhh[256 + k]));
            h[i] = (1.f - z) * n + z * h[i];
        }
        __syncthreads();

        // ---- mma chunk 1 (cols' 192..383) ----
        if (wid < 12) {
            wmma::fragment<wmma::accumulator, 16, 16, 16, float> accA, accB, accC;
            wmma::fill_fragment(accA, 0.f);
            wmma::fill_fragment(accB, 0.f);
            wmma::fill_fragment(accC, 0.f);
            #pragma unroll
            for (int jf = 0; jf < 8; ++jf) {
                wmma::fragment<wmma::matrix_a, 16, 16, 16, __nv_bfloat16, wmma::row_major> aH, aL;
                wmma::fragment<wmma::matrix_b, 16, 16, 16, __nv_bfloat16, wmma::row_major> bH, bL;
                wmma::load_matrix_sync(aH, sHh + jf * 16, LDH);
                wmma::load_matrix_sync(aL, sHl + jf * 16, LDH);
                wmma::load_matrix_sync(bH, sWh + (jf * 16) * LDWP + 192 + wid * 16, LDWP);
                wmma::load_matrix_sync(bL, sWl + (jf * 16) * LDWP + 192 + wid * 16, LDWP);
                wmma::mma_sync(accA, aH, bH, accA);
                wmma::mma_sync(accB, aH, bL, accB);
                wmma::mma_sync(accC, aL, bH, accC);
            }
            #pragma unroll
            for (int e = 0; e < accA.num_elements; ++e)
                accA.x[e] += accB.x[e] + accC.x[e];
            wmma::store_matrix_sync(sEpi + wid * 16, accA, LDEPI, wmma::mem_row_major);
        }
        __syncthreads();

        #pragma unroll
        for (int i = 0; i < 2; ++i) {
            int kk = k0 + i;
            int k = 64 + kk;
            const float* e = sEpi + b * LDEPI + 3 * kk;
            float r = sigf(xr[2 + i] + e[0] + sBhh[k]);
            float z = sigf(xz[2 + i] + e[1] + sBhh[128 + k]);
            float n = tanhfast(xn[2 + i] + r * (e[2] + sBhh[256 + k]));
            h[2 + i] = (1.f - z) * n + z * h[2 + i];
        }

        const size_t orow = ((size_t)(gb0 + b) * SEQ + tt) * H2 + dir * HID;
        #pragma unroll
        for (int i = 0; i < 4; ++i) {
            int k = (i >> 1) * 64 + k0 + (i & 1);
            float v = h[i];
            __nv_bfloat16 hi = __float2bfloat16(v);
            __nv_bfloat16 lo = __float2bfloat16(v - __bfloat162float(hi));
            sHh[b * LDH + k] = hi;
            sHl[b * LDH + k] = lo;
            if (LAYER == 0) {
                houtH[orow + k] = hi;
                houtL[orow + k] = lo;
            } else {
                houtF[orow + k] = v;
            }
        }
        __syncthreads();
    }
}

// ---------------- final head ----------------
__global__ __launch_bounds__(256) void final_kernel(
    const float* __restrict__ h1, const float* __restrict__ Wf,
    const float* __restrict__ bf, float* __restrict__ out)
{
    __shared__ float sW[H2];
    int tid = threadIdx.x;
    sW[tid] = Wf[tid];
    __syncthreads();
    int w = tid >> 5, l = tid & 31;
    size_t row = (size_t)blockIdx.x * 8 + w;
    const float* hr = h1 + row * H2;
    float s = 0.f;
    #pragma unroll
    for (int i = 0; i < 8; ++i)
        s = fmaf(hr[l + i * 32], sW[l + i * 32], s);
    #pragma unroll
    for (int off = 16; off; off >>= 1)
        s += __shfl_xor_sync(0xffffffffu, s, off);
    if (l == 0)
        out[row] = 1.f / (1.f + __expf(-(s + bf[0])));
}

// ---------------- launch ----------------
extern "C" void kernel_launch(void* const* d_in, const int* in_sizes, int n_in,
                              void* d_out, int out_size)
{
    const float* received = (const float*)d_in[0];
    const float* W_lin    = (const float*)d_in[1];
    const float* b_lin    = (const float*)d_in[2];
    const float* Wih0f = (const float*)d_in[3],  *Whh0f = (const float*)d_in[4];
    const float* bih0f = (const float*)d_in[5],  *bhh0f = (const float*)d_in[6];
    const float* Wih0b = (const float*)d_in[7],  *Whh0b = (const float*)d_in[8];
    const float* bih0b = (const float*)d_in[9],  *bhh0b = (const float*)d_in[10];
    const float* Wih1f = (const float*)d_in[11], *Whh1f = (const float*)d_in[12];
    const float* bih1f = (const float*)d_in[13], *bhh1f = (const float*)d_in[14];
    const float* Wih1b = (const float*)d_in[15], *Whh1b = (const float*)d_in[16];
    const float* bih1b = (const float*)d_in[17], *bhh1b = (const float*)d_in[18];
    const float* Wf    = (const float*)d_in[19], *bf    = (const float*)d_in[20];
    float* out = (float*)d_out;

    float *code, *xg1, *h1;
    __nv_bfloat16 *ah, *al;
    cudaGetSymbolAddress((void**)&code, g_code);
    cudaGetSymbolAddress((void**)&ah,   g_ah);
    cudaGetSymbolAddress((void**)&al,   g_al);
    cudaGetSymbolAddress((void**)&xg1,  g_xg1);
    cudaGetSymbolAddress((void**)&h1,   g_h1);

    cudaFuncSetAttribute(gru_tc<0>, cudaFuncAttributeMaxDynamicSharedMemorySize, (int)SMEM_GRUTC);
    cudaFuncSetAttribute(gru_tc<1>, cudaFuncAttributeMaxDynamicSharedMemorySize, (int)SMEM_GRUTC);
    cudaFuncSetAttribute(xgemm3, cudaFuncAttributeMaxDynamicSharedMemorySize, (int)SMEM_X3);

    // 1) dec_linear
    sgemm_nt<<<dim3(BATCH / 64, (NLIN + 63) / 64), 256>>>(
        received, W_lin, b_lin, code, BATCH, NLIN, NLIN);

    // 2) layer-0 bidirectional GRU -> bf16 hi/lo h0
    gru_tc<0><<<dim3(BATCH / TB, 2), 512, SMEM_GRUTC>>>(
        code, nullptr, Wih0f, Wih0b, Whh0f, Whh0b, bih0f, bih0b, bhh0f, bhh0b,
        nullptr, ah, al);

    // 3) layer-1 input projections
    xgemm3<<<dim3(6, 200), 256, SMEM_X3>>>(
        ah, al, Wih1f, Wih1b, bih1f, bih1b, xg1);

    // 4) layer-1 bidirectional GRU
    gru_tc<1><<<dim3(BATCH / TB, 2), 512, SMEM_GRUTC>>>(
        nullptr, xg1, nullptr, nullptr, Whh1f, Whh1b, bih1f, bih1b, bhh1f, bhh1b,
        h1, nullptr, nullptr);

    // 5) output head
    final_kernel<<<BL / 8, 256>>>(h1, Wf, bf, out);
}

// round 12
// speedup vs baseline: 1.1510x; 1.1510x over previous
#include <cuda_runtime.h>
#include <cuda_bf16.h>
#include <mma.h>
#include <math.h>
#include <stdint.h>

using namespace nvcuda;

#define BATCH 1024
#define SEQ   200
#define NLIN  400
#define HID   128
#define H2    256
#define H3    384
#define TB    16
#define BL    (BATCH * SEQ)

// ---------------- scratch (static device globals; no allocation) ----------------
__device__ float g_code[(size_t)BATCH * NLIN];
__device__ __nv_bfloat16 g_ah[(size_t)BL * H2];
__device__ __nv_bfloat16 g_al[(size_t)BL * H2];
__device__ float g_xg1 [(size_t)2 * BL * H3];
__device__ float g_part[(size_t)2 * BL * 32];    // per-lane partial dots (fwd, bwd)

__device__ __forceinline__ float sigf(float x) {
    return 1.f / (1.f + __expf(-x));
}
__device__ __forceinline__ float tanhfast(float x) {
    float e = __expf(-2.f * fabsf(x));
    float t = (1.f - e) / (1.f + e);
    return x < 0.f ? -t : t;
}

// ---------------- small SGEMM for dec_linear ----------------
__global__ __launch_bounds__(256) void sgemm_nt(
    const float* __restrict__ A, const float* __restrict__ B,
    const float* __restrict__ bias, float* __restrict__ C,
    int M, int N, int K)
{
    __shared__ float As[16][65];
    __shared__ float Bs[16][65];
    int tid = threadIdx.x;
    int tx = tid & 15, ty = tid >> 4;
    int bm0 = blockIdx.x * 64, bn0 = blockIdx.y * 64;
    int lrow = tid >> 2;
    int lc4  = (tid & 3) * 4;

    float acc[4][4] = {};

    for (int k0 = 0; k0 < K; k0 += 16) {
        float4 av = *(const float4*)(A + (size_t)(bm0 + lrow) * K + k0 + lc4);
        float4 bv = make_float4(0.f, 0.f, 0.f, 0.f);
        if (bn0 + lrow < N)
            bv = *(const float4*)(B + (size_t)(bn0 + lrow) * K + k0 + lc4);
        As[lc4 + 0][lrow] = av.x; As[lc4 + 1][lrow] = av.y;
        As[lc4 + 2][lrow] = av.z; As[lc4 + 3][lrow] = av.w;
        Bs[lc4 + 0][lrow] = bv.x; Bs[lc4 + 1][lrow] = bv.y;
        Bs[lc4 + 2][lrow] = bv.z; Bs[lc4 + 3][lrow] = bv.w;
        __syncthreads();
        #pragma unroll
        for (int kk = 0; kk < 16; ++kk) {
            float a[4], b[4];
            #pragma unroll
            for (int i = 0; i < 4; ++i) { a[i] = As[kk][ty * 4 + i]; b[i] = Bs[kk][tx * 4 + i]; }
            #pragma unroll
            for (int i = 0; i < 4; ++i)
                #pragma unroll
                for (int j = 0; j < 4; ++j)
                    acc[i][j] = fmaf(a[i], b[j], acc[i][j]);
        }
        __syncthreads();
    }

    #pragma unroll
    for (int i = 0; i < 4; ++i) {
        int row = bm0 + ty * 4 + i;
        #pragma unroll
        for (int j = 0; j < 4; ++j) {
            int col = bn0 + tx * 4 + j;
            if (col < N)
                C[(size_t)row * N + col] = acc[i][j] + bias[col];
        }
    }
}

// ---------------- layer-1 projection GEMM v4: 512 threads, warp tile 32x32 ----------------
// C[2][BL][384] = h0[BL][256] @ Wih1{f,b}[384][256]^T + bias (3-term bf16 hi/lo).
// grid (6, 200); CTA tile 128x128; 16 warps in 4m x 4n grid (4 warps/SMSP for latency hiding).
// K-chunks of 64, double-buffered A (1 sync/chunk), bias preloaded into acc, direct global store.
#define LDW3 264
#define LDA3 72
#define LDB3 132
#define X3_BIAS 0
#define X3_WH   8448
#define X3_WL   (X3_WH  + 128 * LDW3 * 2)
#define X3_AH0  (X3_WL  + 128 * LDW3 * 2)
#define X3_AH1  (X3_AH0 + 128 * LDA3 * 2)
#define X3_AL0  (X3_AH1 + 128 * LDA3 * 2)
#define X3_AL1  (X3_AL0 + 128 * LDA3 * 2)
#define SMEM_X3 (X3_AL1 + 128 * LDA3 * 2)

__global__ __launch_bounds__(512, 1) void xgemm4(
    const __nv_bfloat16* __restrict__ Ah, const __nv_bfloat16* __restrict__ Al,
    const float* __restrict__ Bf, const float* __restrict__ Bb,
    const float* __restrict__ biasf, const float* __restrict__ biasb,
    float* __restrict__ C)
{
    extern __shared__ char smem[];
    float* sBias = (float*)(smem + X3_BIAS);
    __nv_bfloat16* sWh = (__nv_bfloat16*)(smem + X3_WH);
    __nv_bfloat16* sWl = (__nv_bfloat16*)(smem + X3_WL);
    __nv_bfloat16* sAh[2] = { (__nv_bfloat16*)(smem + X3_AH0), (__nv_bfloat16*)(smem + X3_AH1) };
    __nv_bfloat16* sAl[2] = { (__nv_bfloat16*)(smem + X3_AL0), (__nv_bfloat16*)(smem + X3_AL1) };

    const int tid = threadIdx.x;
    const int wid = tid >> 5;
    const int wm = wid & 3;          // rows wm*32
    const int wn = wid >> 2;         // cols wn*32

    const int bx = blockIdx.x;
    const int dir = bx / 3;
    const int ncol0 = (bx % 3) * 128;
    const float* W = dir ? Bb : Bf;
    const float* bias = dir ? biasb : biasf;
    float* Cb = C + (size_t)dir * BL * H3;

    // W tile (128 out-cols x 256 k) -> bf16 hi/lo, once per CTA
    for (int idx = tid; idx < 128 * 256; idx += 512) {
        int n = idx >> 8, k = idx & 255;
        float w = W[(size_t)(ncol0 + n) * H2 + k];
        __nv_bfloat16 hi = __float2bfloat16(w);
        __nv_bfloat16 lo = __float2bfloat16(w - __bfloat162float(hi));
        sWh[n * LDW3 + k] = hi;
        sWl[n * LDW3 + k] = lo;
    }
    for (int idx = tid; idx < 16 * 128; idx += 512) {
        int r = idx >> 7, c = idx & 127;
        sBias[r * LDB3 + c] = bias[ncol0 + c];
    }

    // A prefetch: 512 threads cover 128 rows x 64 cols (16 bf16 each)
    const int pr = tid >> 2;
    const int pc = (tid & 3) * 16;
    uint4 ph[2], pl[2];

    #define FETCH_CHUNK(g) do { \
        int _it = (g) >> 2, _c = (g) & 3; \
        size_t _base = (((size_t)_it * 200 + blockIdx.y) * 128 + pr) * H2 + _c * 64 + pc; \
        ph[0] = *(const uint4*)(Ah + _base); ph[1] = *(const uint4*)(Ah + _base + 8); \
        pl[0] = *(const uint4*)(Al + _base); pl[1] = *(const uint4*)(Al + _base + 8); \
    } while (0)

    FETCH_CHUNK(0);
    __syncthreads();   // W + bias ready

    for (int it = 0; it < 8; ++it) {
        const size_t m0 = ((size_t)it * 200 + blockIdx.y) * 128;

        wmma::fragment<wmma::accumulator, 16, 16, 16, float> acc[2][2];
        #pragma unroll
        for (int i = 0; i < 2; ++i)
            #pragma unroll
            for (int j = 0; j < 2; ++j)
                wmma::load_matrix_sync(acc[i][j], sBias + wn * 32 + j * 16, LDB3, wmma::mem_row_major);

        for (int c = 0; c < 4; ++c) {
            const int g = it * 4 + c;
            const int buf = g & 1;

            __nv_bfloat16* dH = sAh[buf] + pr * LDA3 + pc;
            __nv_bfloat16* dL = sAl[buf] + pr * LDA3 + pc;
            *(uint4*)(dH) = ph[0]; *(uint4*)(dH + 8) = ph[1];
            *(uint4*)(dL) = pl[0]; *(uint4*)(dL + 8) = pl[1];

            if (g + 1 < 32) FETCH_CHUNK(g + 1);
            __syncthreads();   // chunk g visible; all warps past mma g-1

            #pragma unroll
            for (int kk = 0; kk < 4; ++kk) {
                wmma::fragment<wmma::matrix_a, 16, 16, 16, __nv_bfloat16, wmma::row_major> fah[2], fal[2];
                wmma::fragment<wmma::matrix_b, 16, 16, 16, __nv_bfloat16, wmma::col_major> fbh[2], fbl[2];
                #pragma unroll
                for (int i = 0; i < 2; ++i) {
                    wmma::load_matrix_sync(fah[i], sAh[buf] + (wm * 32 + i * 16) * LDA3 + kk * 16, LDA3);
                    wmma::load_matrix_sync(fal[i], sAl[buf] + (wm * 32 + i * 16) * LDA3 + kk * 16, LDA3);
                }
                #pragma unroll
                for (int j = 0; j < 2; ++j) {
                    wmma::load_matrix_sync(fbh[j], sWh + (wn * 32 + j * 16) * LDW3 + c * 64 + kk * 16, LDW3);
                    wmma::load_matrix_sync(fbl[j], sWl + (wn * 32 + j * 16) * LDW3 + c * 64 + kk * 16, LDW3);
                }
                #pragma unroll
                for (int i = 0; i < 2; ++i)
                    #pragma unroll
                    for (int j = 0; j < 2; ++j) {
                        wmma::mma_sync(acc[i][j], fah[i], fbh[j], acc[i][j]);
                        wmma::mma_sync(acc[i][j], fah[i], fbl[j], acc[i][j]);
                        wmma::mma_sync(acc[i][j], fal[i], fbh[j], acc[i][j]);
                    }
            }
        }

        #pragma unroll
        for (int i = 0; i < 2; ++i)
            #pragma unroll
            for (int j = 0; j < 2; ++j)
                wmma::store_matrix_sync(
                    Cb + (m0 + wm * 32 + i * 16) * H3 + ncol0 + wn * 32 + j * 16,
                    acc[i][j], H3, wmma::mem_row_major);
    }
    #undef FETCH_CHUNK
}

// ---------------- tensor-core GRU layer (R10-proven; layer1 fuses output partials) ----------------
#define LDWP 392
#define LDH  136
#define LDEPI 196
#define GOFF_WH  0
#define GOFF_WL  (GOFF_WH + 128 * LDWP * 2)
#define GOFF_HH  (GOFF_WL + 128 * LDWP * 2)
#define GOFF_HL  (GOFF_HH + TB * LDH * 2)
#define GOFF_EPI (GOFF_HL + TB * LDH * 2)
#define GOFF_BHH (GOFF_EPI + TB * LDEPI * 4)
#define GOFF_BIH (GOFF_BHH + H3 * 4)
#define GOFF_WIH (GOFF_BIH + H3 * 4)
#define SMEM_GRUTC (GOFF_WIH + H3 * 2 * 4)

template <int LAYER>
__global__ __launch_bounds__(512, 1) void gru_tc(
    const float* __restrict__ code,
    const float* __restrict__ xg,
    const float* __restrict__ Wih_f, const float* __restrict__ Wih_b,
    const float* __restrict__ Whh_f, const float* __restrict__ Whh_b,
    const float* __restrict__ bih_f, const float* __restrict__ bih_b,
    const float* __restrict__ bhh_f, const float* __restrict__ bhh_b,
    const float* __restrict__ Wf,                  // layer1: final head weights [1,256]
    float* __restrict__ gpart,                     // layer1: [2][BL][32] partial dots
    __nv_bfloat16* __restrict__ houtH,             // layer0: hi
    __nv_bfloat16* __restrict__ houtL)             // layer0: lo
{
    extern __shared__ char smem[];
    __nv_bfloat16* sWh = (__nv_bfloat16*)(smem + GOFF_WH);
    __nv_bfloat16* sWl = (__nv_bfloat16*)(smem + GOFF_WL);
    __nv_bfloat16* sHh = (__nv_bfloat16*)(smem + GOFF_HH);
    __nv_bfloat16* sHl = (__nv_bfloat16*)(smem + GOFF_HL);
    float* sEpi = (float*)(smem + GOFF_EPI);
    float* sBhh = (float*)(smem + GOFF_BHH);
    float* sBih = (float*)(smem + GOFF_BIH);
    float* sWih = (float*)(smem + GOFF_WIH);

    const int tid = threadIdx.x;
    const int dir = blockIdx.y;
    const int gb0 = blockIdx.x * TB;
    const float* Whh = dir ? Whh_b : Whh_f;
    const float* bhh = dir ? bhh_b : bhh_f;

    for (int idx = tid; idx < H3 * HID; idx += 512) {
        int r = idx >> 7, j = idx & 127;
        int g = r >> 7, k = r & 127;
        int colp = (k >> 6) * 192 + 3 * (k & 63) + g;
        float w = Whh[r * HID + j];
        __nv_bfloat16 hi = __float2bfloat16(w);
        __nv_bfloat16 lo = __float2bfloat16(w - __bfloat162float(hi));
        sWh[j * LDWP + colp] = hi;
        sWl[j * LDWP + colp] = lo;
    }
    for (int idx = tid; idx < H3; idx += 512) {
        sBhh[idx] = bhh[idx];
        if (LAYER == 0) {
            const float* Wih = dir ? Wih_b : Wih_f;
            const float* bih = dir ? bih_b : bih_f;
            sBih[idx] = bih[idx];
            sWih[idx * 2 + 0] = Wih[idx * 2 + 0];
            sWih[idx * 2 + 1] = Wih[idx * 2 + 1];
        }
    }
    for (int idx = tid; idx < TB * LDH; idx += 512) {
        sHh[idx] = __float2bfloat16(0.f);
        sHl[idx] = __float2bfloat16(0.f);
    }
    __syncthreads();

    const int wid = tid >> 5, lane = tid & 31;
    const int b = wid;
    const int k0 = lane * 2;
    float h[4] = {0.f, 0.f, 0.f, 0.f};

    float wf[4] = {0.f, 0.f, 0.f, 0.f};
    if (LAYER == 1) {
        #pragma unroll
        for (int i = 0; i < 4; ++i)
            wf[i] = __ldg(&Wf[dir * HID + (i >> 1) * 64 + k0 + (i & 1)]);
    }

    for (int t = 0; t < SEQ; ++t) {
        const int tt = dir ? (SEQ - 1 - t) : t;

        float xr[4], xz[4], xn[4];
        if (LAYER == 1) {
            const float* xp = xg + ((size_t)dir * BL + (size_t)(gb0 + b) * SEQ + tt) * H3;
            float2 v;
            v = *(const float2*)(xp + k0);            xr[0] = v.x; xr[1] = v.y;
            v = *(const float2*)(xp + 64 + k0);       xr[2] = v.x; xr[3] = v.y;
            v = *(const float2*)(xp + 128 + k0);      xz[0] = v.x; xz[1] = v.y;
            v = *(const float2*)(xp + 192 + k0);      xz[2] = v.x; xz[3] = v.y;
            v = *(const float2*)(xp + 256 + k0);      xn[0] = v.x; xn[1] = v.y;
            v = *(const float2*)(xp + 320 + k0);      xn[2] = v.x; xn[3] = v.y;
        } else {
            float c0 = __ldg(&code[(size_t)(gb0 + b) * NLIN + tt * 2 + 0]);
            float c1 = __ldg(&code[(size_t)(gb0 + b) * NLIN + tt * 2 + 1]);
            #pragma unroll
            for (int i = 0; i < 4; ++i) {
                int k = (i >> 1) * 64 + k0 + (i & 1);
                xr[i] = fmaf(c0, sWih[k * 2],           fmaf(c1, sWih[k * 2 + 1],           sBih[k]));
                xz[i] = fmaf(c0, sWih[(128 + k) * 2],   fmaf(c1, sWih[(128 + k) * 2 + 1],   sBih[128 + k]));
                xn[i] = fmaf(c0, sWih[(256 + k) * 2],   fmaf(c1, sWih[(256 + k) * 2 + 1],   sBih[256 + k]));
            }
        }

        wmma::fragment<wmma::matrix_a, 16, 16, 16, __nv_bfloat16, wmma::row_major> aH[8], aL[8];
        if (wid < 12) {
            wmma::fragment<wmma::accumulator, 16, 16, 16, float> acc;
            wmma::fill_fragment(acc, 0.f);
            #pragma unroll
            for (int jf = 0; jf < 8; ++jf) {
                wmma::fragment<wmma::matrix_b, 16, 16, 16, __nv_bfloat16, wmma::row_major> bH, bL;
                wmma::load_matrix_sync(aH[jf], sHh + jf * 16, LDH);
                wmma::load_matrix_sync(aL[jf], sHl + jf * 16, LDH);
                wmma::load_matrix_sync(bH, sWh + (jf * 16) * LDWP + wid * 16, LDWP);
                wmma::load_matrix_sync(bL, sWl + (jf * 16) * LDWP + wid * 16, LDWP);
                wmma::mma_sync(acc, aH[jf], bH, acc);
                wmma::mma_sync(acc, aH[jf], bL, acc);
                wmma::mma_sync(acc, aL[jf], bH, acc);
            }
            wmma::store_matrix_sync(sEpi + wid * 16, acc, LDEPI, wmma::mem_row_major);
        }
        __syncthreads();

        #pragma unroll
        for (int i = 0; i < 2; ++i) {
            int k = k0 + i;
            const float* e = sEpi + b * LDEPI + 3 * k;
            float r = sigf(xr[i] + e[0] + sBhh[k]);
            float z = sigf(xz[i] + e[1] + sBhh[128 + k]);
            float n = tanhfast(xn[i] + r * (e[2] + sBhh[256 + k]));
            h[i] = (1.f - z) * n + z * h[i];
        }
        __syncthreads();

        if (wid < 12) {
            wmma::fragment<wmma::accumulator, 16, 16, 16, float> acc;
            wmma::fill_fragment(acc, 0.f);
            #pragma unroll
            for (int jf = 0; jf < 8; ++jf) {
                wmma::fragment<wmma::matrix_b, 16, 16, 16, __nv_bfloat16, wmma::row_major> bH, bL;
                wmma::load_matrix_sync(bH, sWh + (jf * 16) * LDWP + 192 + wid * 16, LDWP);
                wmma::load_matrix_sync(bL, sWl + (jf * 16) * LDWP + 192 + wid * 16, LDWP);
                wmma::mma_sync(acc, aH[jf], bH, acc);
                wmma::mma_sync(acc, aH[jf], bL, acc);
                wmma::mma_sync(acc, aL[jf], bH, acc);
            }
            wmma::store_matrix_sync(sEpi + wid * 16, acc, LDEPI, wmma::mem_row_major);
        }
        __syncthreads();

        #pragma unroll
        for (int i = 0; i < 2; ++i) {
            int kk = k0 + i;
            int k = 64 + kk;
            const float* e = sEpi + b * LDEPI + 3 * kk;
            float r = sigf(xr[2 + i] + e[0] + sBhh[k]);
            float z = sigf(xz[2 + i] + e[1] + sBhh[128 + k]);
            float n = tanhfast(xn[2 + i] + r * (e[2] + sBhh[256 + k]));
            h[2 + i] = (1.f - z) * n + z * h[2 + i];
        }

        // writeback: smem h (bf16 hi/lo) + (layer0: global h0) / (layer1: head partial)
        const size_t row = (size_t)(gb0 + b) * SEQ + tt;
        #pragma unroll
        for (int i = 0; i < 4; ++i) {
            int k = (i >> 1) * 64 + k0 + (i & 1);
            float v = h[i];
            __nv_bfloat16 hi = __float2bfloat16(v);
            __nv_bfloat16 lo = __float2bfloat16(v - __bfloat162float(hi));
            sHh[b * LDH + k] = hi;
            sHl[b * LDH + k] = lo;
            if (LAYER == 0) {
                houtH[row * H2 + dir * HID + k] = hi;
                houtL[row * H2 + dir * HID + k] = lo;
            }
        }
        if (LAYER == 1) {
            float p = fmaf(h[0], wf[0], fmaf(h[1], wf[1], fmaf(h[2], wf[2], h[3] * wf[3])));
            gpart[((size_t)dir * BL + row) * 32 + lane] = p;
        }
        __syncthreads();
    }
}

// ---------------- final head: out = sigmoid(sum(partF)+sum(partB)+bf) ----------------
__global__ __launch_bounds__(256) void final2(
    const float* __restrict__ part, const float* __restrict__ bf,
    float* __restrict__ out)
{
    size_t i = (size_t)blockIdx.x * 256 + threadIdx.x;   // 0..BL-1
    const float4* p0 = (const float4*)(part + i * 32);
    const float4* p1 = (const float4*)(part + (size_t)BL * 32 + i * 32);
    float s = 0.f;
    #pragma unroll
    for (int q = 0; q < 8; ++q) { float4 v = p0[q]; s += v.x + v.y + v.z + v.w; }
    #pragma unroll
    for (int q = 0; q < 8; ++q) { float4 v = p1[q]; s += v.x + v.y + v.z + v.w; }
    out[i] = 1.f / (1.f + __expf(-(s + bf[0])));
}

// ---------------- launch ----------------
extern "C" void kernel_launch(void* const* d_in, const int* in_sizes, int n_in,
                              void* d_out, int out_size)
{
    const float* received = (const float*)d_in[0];
    const float* W_lin    = (const float*)d_in[1];
    const float* b_lin    = (const float*)d_in[2];
    const float* Wih0f = (const float*)d_in[3],  *Whh0f = (const float*)d_in[4];
    const float* bih0f = (const float*)d_in[5],  *bhh0f = (const float*)d_in[6];
    const float* Wih0b = (const float*)d_in[7],  *Whh0b = (const float*)d_in[8];
    const float* bih0b = (const float*)d_in[9],  *bhh0b = (const float*)d_in[10];
    const float* Wih1f = (const float*)d_in[11], *Whh1f = (const float*)d_in[12];
    const float* bih1f = (const float*)d_in[13], *bhh1f = (const float*)d_in[14];
    const float* Wih1b = (const float*)d_in[15], *Whh1b = (const float*)d_in[16];
    const float* bih1b = (const float*)d_in[17], *bhh1b = (const float*)d_in[18];
    const float* Wf    = (const float*)d_in[19], *bf    = (const float*)d_in[20];
    float* out = (float*)d_out;

    float *code, *xg1, *part;
    __nv_bfloat16 *ah, *al;
    cudaGetSymbolAddress((void**)&code, g_code);
    cudaGetSymbolAddress((void**)&ah,   g_ah);
    cudaGetSymbolAddress((void**)&al,   g_al);
    cudaGetSymbolAddress((void**)&xg1,  g_xg1);
    cudaGetSymbolAddress((void**)&part, g_part);

    cudaFuncSetAttribute(gru_tc<0>, cudaFuncAttributeMaxDynamicSharedMemorySize, (int)SMEM_GRUTC);
    cudaFuncSetAttribute(gru_tc<1>, cudaFuncAttributeMaxDynamicSharedMemorySize, (int)SMEM_GRUTC);
    cudaFuncSetAttribute(xgemm4, cudaFuncAttributeMaxDynamicSharedMemorySize, (int)SMEM_X3);

    // 1) dec_linear
    sgemm_nt<<<dim3(BATCH / 64, (NLIN + 63) / 64), 256>>>(
        received, W_lin, b_lin, code, BATCH, NLIN, NLIN);

    // 2) layer-0 bidirectional GRU -> bf16 hi/lo h0
    gru_tc<0><<<dim3(BATCH / TB, 2), 512, SMEM_GRUTC>>>(
        code, nullptr, Wih0f, Wih0b, Whh0f, Whh0b, bih0f, bih0b, bhh0f, bhh0b,
        nullptr, nullptr, ah, al);

    // 3) layer-1 input projections (16-warp wmma)
    xgemm4<<<dim3(6, 200), 512, SMEM_X3>>>(
        ah, al, Wih1f, Wih1b, bih1f, bih1b, xg1);

    // 4) layer-1 bidirectional GRU with fused head partials
    gru_tc<1><<<dim3(BATCH / TB, 2), 512, SMEM_GRUTC>>>(
        nullptr, xg1, nullptr, nullptr, Whh1f, Whh1b, bih1f, bih1b, bhh1f, bhh1b,
        Wf, part, nullptr, nullptr);

    // 5) output head reduction + sigmoid
    final2<<<BL / 256, 256>>>(part, bf, out);
}

// round 13
// speedup vs baseline: 1.3549x; 1.1772x over previous
#include <cuda_runtime.h>
#include <cuda_bf16.h>
#include <cuda_fp16.h>
#include <mma.h>
#include <math.h>
#include <stdint.h>

using namespace nvcuda;

#define BATCH 1024
#define SEQ   200
#define NLIN  400
#define HID   128
#define H2    256
#define H3    384
#define TB    16
#define BL    (BATCH * SEQ)

// ---------------- scratch (static device globals; no allocation) ----------------
__device__ float g_code[(size_t)BATCH * NLIN];
__device__ __half g_h0h[(size_t)BL * H2];        // h0 as fp16 (|h|<=1, 2^-11 rel)
__device__ float g_xg1 [(size_t)2 * BL * H3];
__device__ float g_part[(size_t)2 * BL * 32];    // per-lane partial dots (fwd, bwd)

__device__ __forceinline__ float sigf(float x) {
    return 1.f / (1.f + __expf(-x));
}
__device__ __forceinline__ float tanhfast(float x) {
    float e = __expf(-2.f * fabsf(x));
    float t = (1.f - e) / (1.f + e);
    return x < 0.f ? -t : t;
}

// ---------------- small SGEMM for dec_linear ----------------
__global__ __launch_bounds__(256) void sgemm_nt(
    const float* __restrict__ A, const float* __restrict__ B,
    const float* __restrict__ bias, float* __restrict__ C,
    int M, int N, int K)
{
    __shared__ float As[16][65];
    __shared__ float Bs[16][65];
    int tid = threadIdx.x;
    int tx = tid & 15, ty = tid >> 4;
    int bm0 = blockIdx.x * 64, bn0 = blockIdx.y * 64;
    int lrow = tid >> 2;
    int lc4  = (tid & 3) * 4;

    float acc[4][4] = {};

    for (int k0 = 0; k0 < K; k0 += 16) {
        float4 av = *(const float4*)(A + (size_t)(bm0 + lrow) * K + k0 + lc4);
        float4 bv = make_float4(0.f, 0.f, 0.f, 0.f);
        if (bn0 + lrow < N)
            bv = *(const float4*)(B + (size_t)(bn0 + lrow) * K + k0 + lc4);
        As[lc4 + 0][lrow] = av.x; As[lc4 + 1][lrow] = av.y;
        As[lc4 + 2][lrow] = av.z; As[lc4 + 3][lrow] = av.w;
        Bs[lc4 + 0][lrow] = bv.x; Bs[lc4 + 1][lrow] = bv.y;
        Bs[lc4 + 2][lrow] = bv.z; Bs[lc4 + 3][lrow] = bv.w;
        __syncthreads();
        #pragma unroll
        for (int kk = 0; kk < 16; ++kk) {
            float a[4], b[4];
            #pragma unroll
            for (int i = 0; i < 4; ++i) { a[i] = As[kk][ty * 4 + i]; b[i] = Bs[kk][tx * 4 + i]; }
            #pragma unroll
            for (int i = 0; i < 4; ++i)
                #pragma unroll
                for (int j = 0; j < 4; ++j)
                    acc[i][j] = fmaf(a[i], b[j], acc[i][j]);
        }
        __syncthreads();
    }

    #pragma unroll
    for (int i = 0; i < 4; ++i) {
        int row = bm0 + ty * 4 + i;
        #pragma unroll
        for (int j = 0; j < 4; ++j) {
            int col = bn0 + tx * 4 + j;
            if (col < N)
                C[(size_t)row * N + col] = acc[i][j] + bias[col];
        }
    }
}

// ---------------- layer-1 projection GEMM v5: fp16 A single, fp16 W hi/lo(scaled) ----------------
// C[2][BL][384] = h0[BL][256] @ Wih1{f,b}[384][256]^T + bias.
// acc = A*Wh + (A*(Wl*2^11))*2^-11 + bias.  grid (6,200), 512 thr = 16 warps (4m x 4n), tile 32x32.
#define LDW5 264
#define LDA5 72
#define LDB5 132
#define X5_BIAS 0
#define X5_WH   8448
#define X5_WL   (X5_WH  + 128 * LDW5 * 2)
#define X5_AH0  (X5_WL  + 128 * LDW5 * 2)
#define X5_AH1  (X5_AH0 + 128 * LDA5 * 2)
#define SMEM_X5 (X5_AH1 + 128 * LDA5 * 2)      // ~180 KB

__global__ __launch_bounds__(512, 1) void xgemm5(
    const __half* __restrict__ A,
    const float* __restrict__ Bf, const float* __restrict__ Bb,
    const float* __restrict__ biasf, const float* __restrict__ biasb,
    float* __restrict__ C)
{
    extern __shared__ char smem[];
    float* sBias = (float*)(smem + X5_BIAS);
    __half* sWh = (__half*)(smem + X5_WH);
    __half* sWl = (__half*)(smem + X5_WL);
    __half* sA[2] = { (__half*)(smem + X5_AH0), (__half*)(smem + X5_AH1) };

    const int tid = threadIdx.x;
    const int wid = tid >> 5;
    const int wm = wid & 3;          // rows wm*32
    const int wn = wid >> 2;         // cols wn*32

    const int bx = blockIdx.x;
    const int dir = bx / 3;
    const int ncol0 = (bx % 3) * 128;
    const float* W = dir ? Bb : Bf;
    const float* bias = dir ? biasb : biasf;
    float* Cb = C + (size_t)dir * BL * H3;

    // W tile (128 out-cols x 256 k) -> fp16 hi + scaled lo
    for (int idx = tid; idx < 128 * 256; idx += 512) {
        int n = idx >> 8, k = idx & 255;
        float w = W[(size_t)(ncol0 + n) * H2 + k];
        __half hi = __float2half_rn(w);
        __half lo = __float2half_rn((w - __half2float(hi)) * 2048.0f);
        sWh[n * LDW5 + k] = hi;
        sWl[n * LDW5 + k] = lo;
    }
    for (int idx = tid; idx < 16 * 128; idx += 512) {
        int r = idx >> 7, c = idx & 127;
        sBias[r * LDB5 + c] = bias[ncol0 + c];
    }

    // A prefetch: 512 threads cover 128 rows x 64 cols (16 fp16 each = 2 uint4)
    const int pr = tid >> 2;
    const int pc = (tid & 3) * 16;
    uint4 ph[2];

    #define FETCH_CHUNK(g) do { \
        int _it = (g) >> 2, _c = (g) & 3; \
        size_t _base = (((size_t)_it * 200 + blockIdx.y) * 128 + pr) * H2 + _c * 64 + pc; \
        ph[0] = *(const uint4*)(A + _base); ph[1] = *(const uint4*)(A + _base + 8); \
    } while (0)

    FETCH_CHUNK(0);
    __syncthreads();   // W + bias ready

    for (int it = 0; it < 8; ++it) {
        const size_t m0 = ((size_t)it * 200 + blockIdx.y) * 128;

        wmma::fragment<wmma::accumulator, 16, 16, 16, float> accH[2][2], accL[2][2];
        #pragma unroll
        for (int i = 0; i < 2; ++i)
            #pragma unroll
            for (int j = 0; j < 2; ++j) {
                wmma::load_matrix_sync(accH[i][j], sBias + wn * 32 + j * 16, LDB5, wmma::mem_row_major);
                wmma::fill_fragment(accL[i][j], 0.f);
            }

        for (int c = 0; c < 4; ++c) {
            const int g = it * 4 + c;
            const int buf = g & 1;

            __half* dA = sA[buf] + pr * LDA5 + pc;
            *(uint4*)(dA) = ph[0]; *(uint4*)(dA + 8) = ph[1];

            if (g + 1 < 32) FETCH_CHUNK(g + 1);
            __syncthreads();   // chunk g visible; all warps past mma g-1

            #pragma unroll
            for (int kk = 0; kk < 4; ++kk) {
                wmma::fragment<wmma::matrix_a, 16, 16, 16, __half, wmma::row_major> fa[2];
                wmma::fragment<wmma::matrix_b, 16, 16, 16, __half, wmma::col_major> fbh[2], fbl[2];
                #pragma unroll
                for (int i = 0; i < 2; ++i)
                    wmma::load_matrix_sync(fa[i], sA[buf] + (wm * 32 + i * 16) * LDA5 + kk * 16, LDA5);
                #pragma unroll
                for (int j = 0; j < 2; ++j) {
                    wmma::load_matrix_sync(fbh[j], sWh + (wn * 32 + j * 16) * LDW5 + c * 64 + kk * 16, LDW5);
                    wmma::load_matrix_sync(fbl[j], sWl + (wn * 32 + j * 16) * LDW5 + c * 64 + kk * 16, LDW5);
                }
                #pragma unroll
                for (int i = 0; i < 2; ++i)
                    #pragma unroll
                    for (int j = 0; j < 2; ++j) {
                        wmma::mma_sync(accH[i][j], fa[i], fbh[j], accH[i][j]);
                        wmma::mma_sync(accL[i][j], fa[i], fbl[j], accL[i][j]);
                    }
            }
        }

        const float inv = 1.0f / 2048.0f;
        #pragma unroll
        for (int i = 0; i < 2; ++i)
            #pragma unroll
            for (int j = 0; j < 2; ++j) {
                #pragma unroll
                for (int e = 0; e < accH[i][j].num_elements; ++e)
                    accH[i][j].x[e] = fmaf(accL[i][j].x[e], inv, accH[i][j].x[e]);
                wmma::store_matrix_sync(
                    Cb + (m0 + wm * 32 + i * 16) * H3 + ncol0 + wn * 32 + j * 16,
                    accH[i][j], H3, wmma::mem_row_major);
            }
    }
    #undef FETCH_CHUNK
}

// ---------------- tensor-core GRU layer (R10/R12-proven; layer1 fuses head partials) ----------------
#define LDWP 392
#define LDH  136
#define LDEPI 196
#define GOFF_WH  0
#define GOFF_WL  (GOFF_WH + 128 * LDWP * 2)
#define GOFF_HH  (GOFF_WL + 128 * LDWP * 2)
#define GOFF_HL  (GOFF_HH + TB * LDH * 2)
#define GOFF_EPI (GOFF_HL + TB * LDH * 2)
#define GOFF_BHH (GOFF_EPI + TB * LDEPI * 4)
#define GOFF_BIH (GOFF_BHH + H3 * 4)
#define GOFF_WIH (GOFF_BIH + H3 * 4)
#define SMEM_GRUTC (GOFF_WIH + H3 * 2 * 4)

template <int LAYER>
__global__ __launch_bounds__(512, 1) void gru_tc(
    const float* __restrict__ code,
    const float* __restrict__ xg,
    const float* __restrict__ Wih_f, const float* __restrict__ Wih_b,
    const float* __restrict__ Whh_f, const float* __restrict__ Whh_b,
    const float* __restrict__ bih_f, const float* __restrict__ bih_b,
    const float* __restrict__ bhh_f, const float* __restrict__ bhh_b,
    const float* __restrict__ Wf,                  // layer1: final head weights [1,256]
    float* __restrict__ gpart,                     // layer1: [2][BL][32] partial dots
    __half* __restrict__ hout)                     // layer0: h0 fp16
{
    extern __shared__ char smem[];
    __nv_bfloat16* sWh = (__nv_bfloat16*)(smem + GOFF_WH);
    __nv_bfloat16* sWl = (__nv_bfloat16*)(smem + GOFF_WL);
    __nv_bfloat16* sHh = (__nv_bfloat16*)(smem + GOFF_HH);
    __nv_bfloat16* sHl = (__nv_bfloat16*)(smem + GOFF_HL);
    float* sEpi = (float*)(smem + GOFF_EPI);
    float* sBhh = (float*)(smem + GOFF_BHH);
    float* sBih = (float*)(smem + GOFF_BIH);
    float* sWih = (float*)(smem + GOFF_WIH);

    const int tid = threadIdx.x;
    const int dir = blockIdx.y;
    const int gb0 = blockIdx.x * TB;
    const float* Whh = dir ? Whh_b : Whh_f;
    const float* bhh = dir ? bhh_b : bhh_f;

    for (int idx = tid; idx < H3 * HID; idx += 512) {
        int r = idx >> 7, j = idx & 127;
        int g = r >> 7, k = r & 127;
        int colp = (k >> 6) * 192 + 3 * (k & 63) + g;
        float w = Whh[r * HID + j];
        __nv_bfloat16 hi = __float2bfloat16(w);
        __nv_bfloat16 lo = __float2bfloat16(w - __bfloat162float(hi));
        sWh[j * LDWP + colp] = hi;
        sWl[j * LDWP + colp] = lo;
    }
    for (int idx = tid; idx < H3; idx += 512) {
        sBhh[idx] = bhh[idx];
        if (LAYER == 0) {
            const float* Wih = dir ? Wih_b : Wih_f;
            const float* bih = dir ? bih_b : bih_f;
            sBih[idx] = bih[idx];
            sWih[idx * 2 + 0] = Wih[idx * 2 + 0];
            sWih[idx * 2 + 1] = Wih[idx * 2 + 1];
        }
    }
    for (int idx = tid; idx < TB * LDH; idx += 512) {
        sHh[idx] = __float2bfloat16(0.f);
        sHl[idx] = __float2bfloat16(0.f);
    }
    __syncthreads();

    const int wid = tid >> 5, lane = tid & 31;
    const int b = wid;
    const int k0 = lane * 2;
    float h[4] = {0.f, 0.f, 0.f, 0.f};

    float wf[4] = {0.f, 0.f, 0.f, 0.f};
    if (LAYER == 1) {
        #pragma unroll
        for (int i = 0; i < 4; ++i)
            wf[i] = __ldg(&Wf[dir * HID + (i >> 1) * 64 + k0 + (i & 1)]);
    }

    for (int t = 0; t < SEQ; ++t) {
        const int tt = dir ? (SEQ - 1 - t) : t;

        float xr[4], xz[4], xn[4];
        if (LAYER == 1) {
            const float* xp = xg + ((size_t)dir * BL + (size_t)(gb0 + b) * SEQ + tt) * H3;
            float2 v;
            v = *(const float2*)(xp + k0);            xr[0] = v.x; xr[1] = v.y;
            v = *(const float2*)(xp + 64 + k0);       xr[2] = v.x; xr[3] = v.y;
            v = *(const float2*)(xp + 128 + k0);      xz[0] = v.x; xz[1] = v.y;
            v = *(const float2*)(xp + 192 + k0);      xz[2] = v.x; xz[3] = v.y;
            v = *(const float2*)(xp + 256 + k0);      xn[0] = v.x; xn[1] = v.y;
            v = *(const float2*)(xp + 320 + k0);      xn[2] = v.x; xn[3] = v.y;
        } else {
            float c0 = __ldg(&code[(size_t)(gb0 + b) * NLIN + tt * 2 + 0]);
            float c1 = __ldg(&code[(size_t)(gb0 + b) * NLIN + tt * 2 + 1]);
            #pragma unroll
            for (int i = 0; i < 4; ++i) {
                int k = (i >> 1) * 64 + k0 + (i & 1);
                xr[i] = fmaf(c0, sWih[k * 2],           fmaf(c1, sWih[k * 2 + 1],           sBih[k]));
                xz[i] = fmaf(c0, sWih[(128 + k) * 2],   fmaf(c1, sWih[(128 + k) * 2 + 1],   sBih[128 + k]));
                xn[i] = fmaf(c0, sWih[(256 + k) * 2],   fmaf(c1, sWih[(256 + k) * 2 + 1],   sBih[256 + k]));
            }
        }

        wmma::fragment<wmma::matrix_a, 16, 16, 16, __nv_bfloat16, wmma::row_major> aH[8], aL[8];
        if (wid < 12) {
            wmma::fragment<wmma::accumulator, 16, 16, 16, float> acc;
            wmma::fill_fragment(acc, 0.f);
            #pragma unroll
            for (int jf = 0; jf < 8; ++jf) {
                wmma::fragment<wmma::matrix_b, 16, 16, 16, __nv_bfloat16, wmma::row_major> bH, bL;
                wmma::load_matrix_sync(aH[jf], sHh + jf * 16, LDH);
                wmma::load_matrix_sync(aL[jf], sHl + jf * 16, LDH);
                wmma::load_matrix_sync(bH, sWh + (jf * 16) * LDWP + wid * 16, LDWP);
                wmma::load_matrix_sync(bL, sWl + (jf * 16) * LDWP + wid * 16, LDWP);
                wmma::mma_sync(acc, aH[jf], bH, acc);
                wmma::mma_sync(acc, aH[jf], bL, acc);
                wmma::mma_sync(acc, aL[jf], bH, acc);
            }
            wmma::store_matrix_sync(sEpi + wid * 16, acc, LDEPI, wmma::mem_row_major);
        }
        __syncthreads();

        #pragma unroll
        for (int i = 0; i < 2; ++i) {
            int k = k0 + i;
            const float* e = sEpi + b * LDEPI + 3 * k;
            float r = sigf(xr[i] + e[0] + sBhh[k]);
            float z = sigf(xz[i] + e[1] + sBhh[128 + k]);
            float n = tanhfast(xn[i] + r * (e[2] + sBhh[256 + k]));
            h[i] = (1.f - z) * n + z * h[i];
        }
        __syncthreads();

        if (wid < 12) {
            wmma::fragment<wmma::accumulator, 16, 16, 16, float> acc;
            wmma::fill_fragment(acc, 0.f);
            #pragma unroll
            for (int jf = 0; jf < 8; ++jf) {
                wmma::fragment<wmma::matrix_b, 16, 16, 16, __nv_bfloat16, wmma::row_major> bH, bL;
                wmma::load_matrix_sync(bH, sWh + (jf * 16) * LDWP + 192 + wid * 16, LDWP);
                wmma::load_matrix_sync(bL, sWl + (jf * 16) * LDWP + 192 + wid * 16, LDWP);
                wmma::mma_sync(acc, aH[jf], bH, acc);
                wmma::mma_sync(acc, aH[jf], bL, acc);
                wmma::mma_sync(acc, aL[jf], bH, acc);
            }
            wmma::store_matrix_sync(sEpi + wid * 16, acc, LDEPI, wmma::mem_row_major);
        }
        __syncthreads();

        #pragma unroll
        for (int i = 0; i < 2; ++i) {
            int kk = k0 + i;
            int k = 64 + kk;
            const float* e = sEpi + b * LDEPI + 3 * kk;
            float r = sigf(xr[2 + i] + e[0] + sBhh[k]);
            float z = sigf(xz[2 + i] + e[1] + sBhh[128 + k]);
            float n = tanhfast(xn[2 + i] + r * (e[2] + sBhh[256 + k]));
            h[2 + i] = (1.f - z) * n + z * h[2 + i];
        }

        // writeback: smem h (bf16 hi/lo) + (layer0: fp16 h0) / (layer1: head partial)
        const size_t row = (size_t)(gb0 + b) * SEQ + tt;
        #pragma unroll
        for (int i = 0; i < 4; ++i) {
            int k = (i >> 1) * 64 + k0 + (i & 1);
            float v = h[i];
            __nv_bfloat16 hi = __float2bfloat16(v);
            __nv_bfloat16 lo = __float2bfloat16(v - __bfloat162float(hi));
            sHh[b * LDH + k] = hi;
            sHl[b * LDH + k] = lo;
        }
        if (LAYER == 0) {
            __half2 p0 = __floats2half2_rn(h[0], h[1]);
            __half2 p1 = __floats2half2_rn(h[2], h[3]);
            *(__half2*)&hout[row * H2 + dir * HID + k0]      = p0;
            *(__half2*)&hout[row * H2 + dir * HID + 64 + k0] = p1;
        } else {
            float p = fmaf(h[0], wf[0], fmaf(h[1], wf[1], fmaf(h[2], wf[2], h[3] * wf[3])));
            gpart[((size_t)dir * BL + row) * 32 + lane] = p;
        }
        __syncthreads();
    }
}

// ---------------- final head: out = sigmoid(sum(partF)+sum(partB)+bf) ----------------
__global__ __launch_bounds__(256) void final2(
    const float* __restrict__ part, const float* __restrict__ bf,
    float* __restrict__ out)
{
    size_t i = (size_t)blockIdx.x * 256 + threadIdx.x;   // 0..BL-1
    const float4* p0 = (const float4*)(part + i * 32);
    const float4* p1 = (const float4*)(part + (size_t)BL * 32 + i * 32);
    float s = 0.f;
    #pragma unroll
    for (int q = 0; q < 8; ++q) { float4 v = p0[q]; s += v.x + v.y + v.z + v.w; }
    #pragma unroll
    for (int q = 0; q < 8; ++q) { float4 v = p1[q]; s += v.x + v.y + v.z + v.w; }
    out[i] = 1.f / (1.f + __expf(-(s + bf[0])));
}

// ---------------- launch ----------------
extern "C" void kernel_launch(void* const* d_in, const int* in_sizes, int n_in,
                              void* d_out, int out_size)
{
    const float* received = (const float*)d_in[0];
    const float* W_lin    = (const float*)d_in[1];
    const float* b_lin    = (const float*)d_in[2];
    const float* Wih0f = (const float*)d_in[3],  *Whh0f = (const float*)d_in[4];
    const float* bih0f = (const float*)d_in[5],  *bhh0f = (const float*)d_in[6];
    const float* Wih0b = (const float*)d_in[7],  *Whh0b = (const float*)d_in[8];
    const float* bih0b = (const float*)d_in[9],  *bhh0b = (const float*)d_in[10];
    const float* Wih1f = (const float*)d_in[11], *Whh1f = (const float*)d_in[12];
    const float* bih1f = (const float*)d_in[13], *bhh1f = (const float*)d_in[14];
    const float* Wih1b = (const float*)d_in[15], *Whh1b = (const float*)d_in[16];
    const float* bih1b = (const float*)d_in[17], *bhh1b = (const float*)d_in[18];
    const float* Wf    = (const float*)d_in[19], *bf    = (const float*)d_in[20];
    float* out = (float*)d_out;

    float *code, *xg1, *part;
    __half *h0h;
    cudaGetSymbolAddress((void**)&code, g_code);
    cudaGetSymbolAddress((void**)&h0h,  g_h0h);
    cudaGetSymbolAddress((void**)&xg1,  g_xg1);
    cudaGetSymbolAddress((void**)&part, g_part);

    cudaFuncSetAttribute(gru_tc<0>, cudaFuncAttributeMaxDynamicSharedMemorySize, (int)SMEM_GRUTC);
    cudaFuncSetAttribute(gru_tc<1>, cudaFuncAttributeMaxDynamicSharedMemorySize, (int)SMEM_GRUTC);
    cudaFuncSetAttribute(xgemm5, cudaFuncAttributeMaxDynamicSharedMemorySize, (int)SMEM_X5);

    // 1) dec_linear
    sgemm_nt<<<dim3(BATCH / 64, (NLIN + 63) / 64), 256>>>(
        received, W_lin, b_lin, code, BATCH, NLIN, NLIN);

    // 2) layer-0 bidirectional GRU -> fp16 h0
    gru_tc<0><<<dim3(BATCH / TB, 2), 512, SMEM_GRUTC>>>(
        code, nullptr, Wih0f, Wih0b, Whh0f, Whh0b, bih0f, bih0b, bhh0f, bhh0b,
        nullptr, nullptr, h0h);

    // 3) layer-1 input projections (fp16 A single, fp16 W hi/lo scaled)
    xgemm5<<<dim3(6, 200), 512, SMEM_X5>>>(
        h0h, Wih1f, Wih1b, bih1f, bih1b, xg1);

    // 4) layer-1 bidirectional GRU with fused head partials
    gru_tc<1><<<dim3(BATCH / TB, 2), 512, SMEM_GRUTC>>>(
        nullptr, xg1, nullptr, nullptr, Whh1f, Whh1b, bih1f, bih1b, bhh1f, bhh1b,
        Wf, part, nullptr);

    // 5) output head reduction + sigmoid
    final2<<<BL / 256, 256>>>(part, bf, out);
}

// round 14
// speedup vs baseline: 1.8410x; 1.3587x over previous
#include <cuda_runtime.h>
#include <cuda_bf16.h>
#include <cuda_fp16.h>
#include <mma.h>
#include <math.h>
#include <stdint.h>

using namespace nvcuda;

#define BATCH 1024
#define SEQ   200
#define NLIN  400
#define HID   128
#define H2    256
#define H3    384
#define TB    16
#define BL    (BATCH * SEQ)

// ---------------- scratch (static device globals; no allocation) ----------------
__device__ float g_code[(size_t)BATCH * NLIN];
__device__ __half g_h0h[(size_t)BL * H2];        // h0 as fp16 (|h|<=1)
__device__ float g_xg1 [(size_t)2 * BL * H3];
__device__ float g_part[(size_t)2 * BL * 32];    // per-lane partial dots (fwd, bwd)

__device__ __forceinline__ float sigf(float x) {
    return 1.f / (1.f + __expf(-x));
}
__device__ __forceinline__ float tanhfast(float x) {
    float e = __expf(-2.f * fabsf(x));
    float t = (1.f - e) / (1.f + e);
    return x < 0.f ? -t : t;
}

// ---------------- small SGEMM for dec_linear ----------------
__global__ __launch_bounds__(256) void sgemm_nt(
    const float* __restrict__ A, const float* __restrict__ B,
    const float* __restrict__ bias, float* __restrict__ C,
    int M, int N, int K)
{
    __shared__ float As[16][65];
    __shared__ float Bs[16][65];
    int tid = threadIdx.x;
    int tx = tid & 15, ty = tid >> 4;
    int bm0 = blockIdx.x * 64, bn0 = blockIdx.y * 64;
    int lrow = tid >> 2;
    int lc4  = (tid & 3) * 4;

    float acc[4][4] = {};

    for (int k0 = 0; k0 < K; k0 += 16) {
        float4 av = *(const float4*)(A + (size_t)(bm0 + lrow) * K + k0 + lc4);
        float4 bv = make_float4(0.f, 0.f, 0.f, 0.f);
        if (bn0 + lrow < N)
            bv = *(const float4*)(B + (size_t)(bn0 + lrow) * K + k0 + lc4);
        As[lc4 + 0][lrow] = av.x; As[lc4 + 1][lrow] = av.y;
        As[lc4 + 2][lrow] = av.z; As[lc4 + 3][lrow] = av.w;
        Bs[lc4 + 0][lrow] = bv.x; Bs[lc4 + 1][lrow] = bv.y;
        Bs[lc4 + 2][lrow] = bv.z; Bs[lc4 + 3][lrow] = bv.w;
        __syncthreads();
        #pragma unroll
        for (int kk = 0; kk < 16; ++kk) {
            float a[4], b[4];
            #pragma unroll
            for (int i = 0; i < 4; ++i) { a[i] = As[kk][ty * 4 + i]; b[i] = Bs[kk][tx * 4 + i]; }
            #pragma unroll
            for (int i = 0; i < 4; ++i)
                #pragma unroll
                for (int j = 0; j < 4; ++j)
                    acc[i][j] = fmaf(a[i], b[j], acc[i][j]);
        }
        __syncthreads();
    }

    #pragma unroll
    for (int i = 0; i < 4; ++i) {
        int row = bm0 + ty * 4 + i;
        #pragma unroll
        for (int j = 0; j < 4; ++j) {
            int col = bn0 + tx * 4 + j;
            if (col < N)
                C[(size_t)row * N + col] = acc[i][j] + bias[col];
        }
    }
}

// ---------------- layer-1 projection GEMM v5 (R13-proven, unchanged) ----------------
#define LDW5 264
#define LDA5 72
#define LDB5 132
#define X5_BIAS 0
#define X5_WH   8448
#define X5_WL   (X5_WH  + 128 * LDW5 * 2)
#define X5_AH0  (X5_WL  + 128 * LDW5 * 2)
#define X5_AH1  (X5_AH0 + 128 * LDA5 * 2)
#define SMEM_X5 (X5_AH1 + 128 * LDA5 * 2)

__global__ __launch_bounds__(512, 1) void xgemm5(
    const __half* __restrict__ A,
    const float* __restrict__ Bf, const float* __restrict__ Bb,
    const float* __restrict__ biasf, const float* __restrict__ biasb,
    float* __restrict__ C)
{
    extern __shared__ char smem[];
    float* sBias = (float*)(smem + X5_BIAS);
    __half* sWh = (__half*)(smem + X5_WH);
    __half* sWl = (__half*)(smem + X5_WL);
    __half* sA[2] = { (__half*)(smem + X5_AH0), (__half*)(smem + X5_AH1) };

    const int tid = threadIdx.x;
    const int wid = tid >> 5;
    const int wm = wid & 3;
    const int wn = wid >> 2;

    const int bx = blockIdx.x;
    const int dir = bx / 3;
    const int ncol0 = (bx % 3) * 128;
    const float* W = dir ? Bb : Bf;
    const float* bias = dir ? biasb : biasf;
    float* Cb = C + (size_t)dir * BL * H3;

    for (int idx = tid; idx < 128 * 256; idx += 512) {
        int n = idx >> 8, k = idx & 255;
        float w = W[(size_t)(ncol0 + n) * H2 + k];
        __half hi = __float2half_rn(w);
        __half lo = __float2half_rn((w - __half2float(hi)) * 2048.0f);
        sWh[n * LDW5 + k] = hi;
        sWl[n * LDW5 + k] = lo;
    }
    for (int idx = tid; idx < 16 * 128; idx += 512) {
        int r = idx >> 7, c = idx & 127;
        sBias[r * LDB5 + c] = bias[ncol0 + c];
    }

    const int pr = tid >> 2;
    const int pc = (tid & 3) * 16;
    uint4 ph[2];

    #define FETCH_CHUNK(g) do { \
        int _it = (g) >> 2, _c = (g) & 3; \
        size_t _base = (((size_t)_it * 200 + blockIdx.y) * 128 + pr) * H2 + _c * 64 + pc; \
        ph[0] = *(const uint4*)(A + _base); ph[1] = *(const uint4*)(A + _base + 8); \
    } while (0)

    FETCH_CHUNK(0);
    __syncthreads();

    for (int it = 0; it < 8; ++it) {
        const size_t m0 = ((size_t)it * 200 + blockIdx.y) * 128;

        wmma::fragment<wmma::accumulator, 16, 16, 16, float> accH[2][2], accL[2][2];
        #pragma unroll
        for (int i = 0; i < 2; ++i)
            #pragma unroll
            for (int j = 0; j < 2; ++j) {
                wmma::load_matrix_sync(accH[i][j], sBias + wn * 32 + j * 16, LDB5, wmma::mem_row_major);
                wmma::fill_fragment(accL[i][j], 0.f);
            }

        for (int c = 0; c < 4; ++c) {
            const int g = it * 4 + c;
            const int buf = g & 1;

            __half* dA = sA[buf] + pr * LDA5 + pc;
            *(uint4*)(dA) = ph[0]; *(uint4*)(dA + 8) = ph[1];

            if (g + 1 < 32) FETCH_CHUNK(g + 1);
            __syncthreads();

            #pragma unroll
            for (int kk = 0; kk < 4; ++kk) {
                wmma::fragment<wmma::matrix_a, 16, 16, 16, __half, wmma::row_major> fa[2];
                wmma::fragment<wmma::matrix_b, 16, 16, 16, __half, wmma::col_major> fbh[2], fbl[2];
                #pragma unroll
                for (int i = 0; i < 2; ++i)
                    wmma::load_matrix_sync(fa[i], sA[buf] + (wm * 32 + i * 16) * LDA5 + kk * 16, LDA5);
                #pragma unroll
                for (int j = 0; j < 2; ++j) {
                    wmma::load_matrix_sync(fbh[j], sWh + (wn * 32 + j * 16) * LDW5 + c * 64 + kk * 16, LDW5);
                    wmma::load_matrix_sync(fbl[j], sWl + (wn * 32 + j * 16) * LDW5 + c * 64 + kk * 16, LDW5);
                }
                #pragma unroll
                for (int i = 0; i < 2; ++i)
                    #pragma unroll
                    for (int j = 0; j < 2; ++j) {
                        wmma::mma_sync(accH[i][j], fa[i], fbh[j], accH[i][j]);
                        wmma::mma_sync(accL[i][j], fa[i], fbl[j], accL[i][j]);
                    }
            }
        }

        const float inv = 1.0f / 2048.0f;
        #pragma unroll
        for (int i = 0; i < 2; ++i)
            #pragma unroll
            for (int j = 0; j < 2; ++j) {
                #pragma unroll
                for (int e = 0; e < accH[i][j].num_elements; ++e)
                    accH[i][j].x[e] = fmaf(accL[i][j].x[e], inv, accH[i][j].x[e]);
                wmma::store_matrix_sync(
                    Cb + (m0 + wm * 32 + i * 16) * H3 + ncol0 + wn * 32 + j * 16,
                    accH[i][j], H3, wmma::mem_row_major);
            }
    }
    #undef FETCH_CHUNK
}

// ---------------- tensor-core GRU layer: fp16 h (single) x fp16 Whh (hi + scaled lo) ----------------
#define LDWP 392
#define LDH  136
#define LDEPI 196
#define GOFF_WH  0
#define GOFF_WL  (GOFF_WH + 128 * LDWP * 2)      // 100352
#define GOFF_H   (GOFF_WL + 128 * LDWP * 2)      // 200704
#define GOFF_EPI (GOFF_H  + TB * LDH * 2)        // 205056
#define GOFF_BHH (GOFF_EPI + TB * LDEPI * 4)     // 217600
#define GOFF_BIH (GOFF_BHH + H3 * 4)             // 219136
#define GOFF_WIH (GOFF_BIH + H3 * 4)             // 220672
#define SMEM_GRUTC (GOFF_WIH + H3 * 2 * 4)       // 223744

template <int LAYER>
__global__ __launch_bounds__(512, 1) void gru_tc(
    const float* __restrict__ code,
    const float* __restrict__ xg,
    const float* __restrict__ Wih_f, const float* __restrict__ Wih_b,
    const float* __restrict__ Whh_f, const float* __restrict__ Whh_b,
    const float* __restrict__ bih_f, const float* __restrict__ bih_b,
    const float* __restrict__ bhh_f, const float* __restrict__ bhh_b,
    const float* __restrict__ Wf,                  // layer1: final head weights [1,256]
    float* __restrict__ gpart,                     // layer1: [2][BL][32] partial dots
    __half* __restrict__ hout)                     // layer0: h0 fp16
{
    extern __shared__ char smem[];
    __half* sWh = (__half*)(smem + GOFF_WH);
    __half* sWl = (__half*)(smem + GOFF_WL);
    __half* sH  = (__half*)(smem + GOFF_H);
    float* sEpi = (float*)(smem + GOFF_EPI);
    float* sBhh = (float*)(smem + GOFF_BHH);
    float* sBih = (float*)(smem + GOFF_BIH);
    float* sWih = (float*)(smem + GOFF_WIH);

    const int tid = threadIdx.x;
    const int dir = blockIdx.y;
    const int gb0 = blockIdx.x * TB;
    const float* Whh = dir ? Whh_b : Whh_f;
    const float* bhh = dir ? bhh_b : bhh_f;

    // Whh -> permuted fp16 hi + 2^11-scaled lo: col' = (k>>6)*192 + 3*(k&63) + g
    for (int idx = tid; idx < H3 * HID; idx += 512) {
        int r = idx >> 7, j = idx & 127;
        int g = r >> 7, k = r & 127;
        int colp = (k >> 6) * 192 + 3 * (k & 63) + g;
        float w = Whh[r * HID + j];
        __half hi = __float2half_rn(w);
        __half lo = __float2half_rn((w - __half2float(hi)) * 2048.0f);
        sWh[j * LDWP + colp] = hi;
        sWl[j * LDWP + colp] = lo;
    }
    for (int idx = tid; idx < H3; idx += 512) {
        sBhh[idx] = bhh[idx];
        if (LAYER == 0) {
            const float* Wih = dir ? Wih_b : Wih_f;
            const float* bih = dir ? bih_b : bih_f;
            sBih[idx] = bih[idx];
            sWih[idx * 2 + 0] = Wih[idx * 2 + 0];
            sWih[idx * 2 + 1] = Wih[idx * 2 + 1];
        }
    }
    for (int idx = tid; idx < TB * LDH; idx += 512)
        sH[idx] = __float2half_rn(0.f);
    __syncthreads();

    const int wid = tid >> 5, lane = tid & 31;
    const int b = wid;
    const int k0 = lane * 2;
    float h[4] = {0.f, 0.f, 0.f, 0.f};
    const float inv2048 = 1.0f / 2048.0f;

    float wf[4] = {0.f, 0.f, 0.f, 0.f};
    if (LAYER == 1) {
        #pragma unroll
        for (int i = 0; i < 4; ++i)
            wf[i] = __ldg(&Wf[dir * HID + (i >> 1) * 64 + k0 + (i & 1)]);
    }

    for (int t = 0; t < SEQ; ++t) {
        const int tt = dir ? (SEQ - 1 - t) : t;

        float xr[4], xz[4], xn[4];
        if (LAYER == 1) {
            const float* xp = xg + ((size_t)dir * BL + (size_t)(gb0 + b) * SEQ + tt) * H3;
            float2 v;
            v = *(const float2*)(xp + k0);            xr[0] = v.x; xr[1] = v.y;
            v = *(const float2*)(xp + 64 + k0);       xr[2] = v.x; xr[3] = v.y;
            v = *(const float2*)(xp + 128 + k0);      xz[0] = v.x; xz[1] = v.y;
            v = *(const float2*)(xp + 192 + k0);      xz[2] = v.x; xz[3] = v.y;
            v = *(const float2*)(xp + 256 + k0);      xn[0] = v.x; xn[1] = v.y;
            v = *(const float2*)(xp + 320 + k0);      xn[2] = v.x; xn[3] = v.y;
        } else {
            float c0 = __ldg(&code[(size_t)(gb0 + b) * NLIN + tt * 2 + 0]);
            float c1 = __ldg(&code[(size_t)(gb0 + b) * NLIN + tt * 2 + 1]);
            #pragma unroll
            for (int i = 0; i < 4; ++i) {
                int k = (i >> 1) * 64 + k0 + (i & 1);
                xr[i] = fmaf(c0, sWih[k * 2],           fmaf(c1, sWih[k * 2 + 1],           sBih[k]));
                xz[i] = fmaf(c0, sWih[(128 + k) * 2],   fmaf(c1, sWih[(128 + k) * 2 + 1],   sBih[128 + k]));
                xn[i] = fmaf(c0, sWih[(256 + k) * 2],   fmaf(c1, sWih[(256 + k) * 2 + 1],   sBih[256 + k]));
            }
        }

        // ---- mma chunk 0 (cols' 0..191): a-frags persist for chunk 1 ----
        wmma::fragment<wmma::matrix_a, 16, 16, 16, __half, wmma::row_major> aF[8];
        if (wid < 12) {
            wmma::fragment<wmma::accumulator, 16, 16, 16, float> accH, accL;
            wmma::fill_fragment(accH, 0.f);
            wmma::fill_fragment(accL, 0.f);
            #pragma unroll
            for (int jf = 0; jf < 8; ++jf) {
                wmma::fragment<wmma::matrix_b, 16, 16, 16, __half, wmma::row_major> bH, bL;
                wmma::load_matrix_sync(aF[jf], sH + jf * 16, LDH);
                wmma::load_matrix_sync(bH, sWh + (jf * 16) * LDWP + wid * 16, LDWP);
                wmma::load_matrix_sync(bL, sWl + (jf * 16) * LDWP + wid * 16, LDWP);
                wmma::mma_sync(accH, aF[jf], bH, accH);
                wmma::mma_sync(accL, aF[jf], bL, accL);
            }
            #pragma unroll
            for (int e = 0; e < accH.num_elements; ++e)
                accH.x[e] = fmaf(accL.x[e], inv2048, accH.x[e]);
            wmma::store_matrix_sync(sEpi + wid * 16, accH, LDEPI, wmma::mem_row_major);
        }
        __syncthreads();

        #pragma unroll
        for (int i = 0; i < 2; ++i) {
            int k = k0 + i;
            const float* e = sEpi + b * LDEPI + 3 * k;
            float r = sigf(xr[i] + e[0] + sBhh[k]);
            float z = sigf(xz[i] + e[1] + sBhh[128 + k]);
            float n = tanhfast(xn[i] + r * (e[2] + sBhh[256 + k]));
            h[i] = (1.f - z) * n + z * h[i];
        }
        __syncthreads();

        // ---- mma chunk 1 (cols' 192..383), reuses aF ----
        if (wid < 12) {
            wmma::fragment<wmma::accumulator, 16, 16, 16, float> accH, accL;
            wmma::fill_fragment(accH, 0.f);
            wmma::fill_fragment(accL, 0.f);
            #pragma unroll
            for (int jf = 0; jf < 8; ++jf) {
                wmma::fragment<wmma::matrix_b, 16, 16, 16, __half, wmma::row_major> bH, bL;
                wmma::load_matrix_sync(bH, sWh + (jf * 16) * LDWP + 192 + wid * 16, LDWP);
                wmma::load_matrix_sync(bL, sWl + (jf * 16) * LDWP + 192 + wid * 16, LDWP);
                wmma::mma_sync(accH, aF[jf], bH, accH);
                wmma::mma_sync(accL, aF[jf], bL, accL);
            }
            #pragma unroll
            for (int e = 0; e < accH.num_elements; ++e)
                accH.x[e] = fmaf(accL.x[e], inv2048, accH.x[e]);
            wmma::store_matrix_sync(sEpi + wid * 16, accH, LDEPI, wmma::mem_row_major);
        }
        __syncthreads();

        #pragma unroll
        for (int i = 0; i < 2; ++i) {
            int kk = k0 + i;
            int k = 64 + kk;
            const float* e = sEpi + b * LDEPI + 3 * kk;
            float r = sigf(xr[2 + i] + e[0] + sBhh[k]);
            float z = sigf(xz[2 + i] + e[1] + sBhh[128 + k]);
            float n = tanhfast(xn[2 + i] + r * (e[2] + sBhh[256 + k]));
            h[2 + i] = (1.f - z) * n + z * h[2 + i];
        }

        // writeback: smem h (fp16) + (layer0: fp16 h0) / (layer1: head partial)
        const size_t row = (size_t)(gb0 + b) * SEQ + tt;
        __half2 p0 = __floats2half2_rn(h[0], h[1]);
        __half2 p1 = __floats2half2_rn(h[2], h[3]);
        *(__half2*)&sH[b * LDH + k0]      = p0;
        *(__half2*)&sH[b * LDH + 64 + k0] = p1;
        if (LAYER == 0) {
            *(__half2*)&hout[row * H2 + dir * HID + k0]      = p0;
            *(__half2*)&hout[row * H2 + dir * HID + 64 + k0] = p1;
        } else {
            float p = fmaf(h[0], wf[0], fmaf(h[1], wf[1], fmaf(h[2], wf[2], h[3] * wf[3])));
            gpart[((size_t)dir * BL + row) * 32 + lane] = p;
        }
        __syncthreads();
    }
}

// ---------------- final head: out = sigmoid(sum(partF)+sum(partB)+bf) ----------------
__global__ __launch_bounds__(256) void final2(
    const float* __restrict__ part, const float* __restrict__ bf,
    float* __restrict__ out)
{
    size_t i = (size_t)blockIdx.x * 256 + threadIdx.x;   // 0..BL-1
    const float4* p0 = (const float4*)(part + i * 32);
    const float4* p1 = (const float4*)(part + (size_t)BL * 32 + i * 32);
    float s = 0.f;
    #pragma unroll
    for (int q = 0; q < 8; ++q) { float4 v = p0[q]; s += v.x + v.y + v.z + v.w; }
    #pragma unroll
    for (int q = 0; q < 8; ++q) { float4 v = p1[q]; s += v.x + v.y + v.z + v.w; }
    out[i] = 1.f / (1.f + __expf(-(s + bf[0])));
}

// ---------------- launch ----------------
extern "C" void kernel_launch(void* const* d_in, const int* in_sizes, int n_in,
                              void* d_out, int out_size)
{
    const float* received = (const float*)d_in[0];
    const float* W_lin    = (const float*)d_in[1];
    const float* b_lin    = (const float*)d_in[2];
    const float* Wih0f = (const float*)d_in[3],  *Whh0f = (const float*)d_in[4];
    const float* bih0f = (const float*)d_in[5],  *bhh0f = (const float*)d_in[6];
    const float* Wih0b = (const float*)d_in[7],  *Whh0b = (const float*)d_in[8];
    const float* bih0b = (const float*)d_in[9],  *bhh0b = (const float*)d_in[10];
    const float* Wih1f = (const float*)d_in[11], *Whh1f = (const float*)d_in[12];
    const float* bih1f = (const float*)d_in[13], *bhh1f = (const float*)d_in[14];
    const float* Wih1b = (const float*)d_in[15], *Whh1b = (const float*)d_in[16];
    const float* bih1b = (const float*)d_in[17], *bhh1b = (const float*)d_in[18];
    const float* Wf    = (const float*)d_in[19], *bf    = (const float*)d_in[20];
    float* out = (float*)d_out;

    float *code, *xg1, *part;
    __half *h0h;
    cudaGetSymbolAddress((void**)&code, g_code);
    cudaGetSymbolAddress((void**)&h0h,  g_h0h);
    cudaGetSymbolAddress((void**)&xg1,  g_xg1);
    cudaGetSymbolAddress((void**)&part, g_part);

    cudaFuncSetAttribute(gru_tc<0>, cudaFuncAttributeMaxDynamicSharedMemorySize, (int)SMEM_GRUTC);
    cudaFuncSetAttribute(gru_tc<1>, cudaFuncAttributeMaxDynamicSharedMemorySize, (int)SMEM_GRUTC);
    cudaFuncSetAttribute(xgemm5, cudaFuncAttributeMaxDynamicSharedMemorySize, (int)SMEM_X5);

    // 1) dec_linear
    sgemm_nt<<<dim3(BATCH / 64, (NLIN + 63) / 64), 256>>>(
        received, W_lin, b_lin, code, BATCH, NLIN, NLIN);

    // 2) layer-0 bidirectional GRU (fp16 TC recurrence) -> fp16 h0
    gru_tc<0><<<dim3(BATCH / TB, 2), 512, SMEM_GRUTC>>>(
        code, nullptr, Wih0f, Wih0b, Whh0f, Whh0b, bih0f, bih0b, bhh0f, bhh0b,
        nullptr, nullptr, h0h);

    // 3) layer-1 input projections (fp16 A single, fp16 W hi/lo scaled)
    xgemm5<<<dim3(6, 200), 512, SMEM_X5>>>(
        h0h, Wih1f, Wih1b, bih1f, bih1b, xg1);

    // 4) layer-1 bidirectional GRU with fused head partials
    gru_tc<1><<<dim3(BATCH / TB, 2), 512, SMEM_GRUTC>>>(
        nullptr, xg1, nullptr, nullptr, Whh1f, Whh1b, bih1f, bih1b, bhh1f, bhh1b,
        Wf, part, nullptr);

    // 5) output head reduction + sigmoid
    final2<<<BL / 256, 256>>>(part, bf, out);
}

// round 15
// speedup vs baseline: 1.9808x; 1.0759x over previous
#include <cuda_runtime.h>
#include <cuda_bf16.h>
#include <cuda_fp16.h>
#include <mma.h>
#include <math.h>
#include <stdint.h>

using namespace nvcuda;

#define BATCH 1024
#define SEQ   200
#define NLIN  400
#define HID   128
#define H2    256
#define H3    384
#define TB    16
#define BL    (BATCH * SEQ)

// ---------------- scratch (static device globals; no allocation) ----------------
__device__ float g_code[(size_t)BATCH * NLIN];
__device__ __half g_h0h[(size_t)BL * H2];        // h0 as fp16 (|h|<=1)
__device__ float g_xg1 [(size_t)2 * BL * H3];
__device__ float g_part[(size_t)2 * BL * 32];    // per-lane partial dots (fwd, bwd)

__device__ __forceinline__ float sigf(float x) {
    return 1.f / (1.f + __expf(-x));
}
__device__ __forceinline__ float tanhfast(float x) {
    float e = __expf(-2.f * fabsf(x));
    float t = (1.f - e) / (1.f + e);
    return x < 0.f ? -t : t;
}

// ---------------- small SGEMM for dec_linear ----------------
__global__ __launch_bounds__(256) void sgemm_nt(
    const float* __restrict__ A, const float* __restrict__ B,
    const float* __restrict__ bias, float* __restrict__ C,
    int M, int N, int K)
{
    __shared__ float As[16][65];
    __shared__ float Bs[16][65];
    int tid = threadIdx.x;
    int tx = tid & 15, ty = tid >> 4;
    int bm0 = blockIdx.x * 64, bn0 = blockIdx.y * 64;
    int lrow = tid >> 2;
    int lc4  = (tid & 3) * 4;

    float acc[4][4] = {};

    for (int k0 = 0; k0 < K; k0 += 16) {
        float4 av = *(const float4*)(A + (size_t)(bm0 + lrow) * K + k0 + lc4);
        float4 bv = make_float4(0.f, 0.f, 0.f, 0.f);
        if (bn0 + lrow < N)
            bv = *(const float4*)(B + (size_t)(bn0 + lrow) * K + k0 + lc4);
        As[lc4 + 0][lrow] = av.x; As[lc4 + 1][lrow] = av.y;
        As[lc4 + 2][lrow] = av.z; As[lc4 + 3][lrow] = av.w;
        Bs[lc4 + 0][lrow] = bv.x; Bs[lc4 + 1][lrow] = bv.y;
        Bs[lc4 + 2][lrow] = bv.z; Bs[lc4 + 3][lrow] = bv.w;
        __syncthreads();
        #pragma unroll
        for (int kk = 0; kk < 16; ++kk) {
            float a[4], b[4];
            #pragma unroll
            for (int i = 0; i < 4; ++i) { a[i] = As[kk][ty * 4 + i]; b[i] = Bs[kk][tx * 4 + i]; }
            #pragma unroll
            for (int i = 0; i < 4; ++i)
                #pragma unroll
                for (int j = 0; j < 4; ++j)
                    acc[i][j] = fmaf(a[i], b[j], acc[i][j]);
        }
        __syncthreads();
    }

    #pragma unroll
    for (int i = 0; i < 4; ++i) {
        int row = bm0 + ty * 4 + i;
        #pragma unroll
        for (int j = 0; j < 4; ++j) {
            int col = bn0 + tx * 4 + j;
            if (col < N)
                C[(size_t)row * N + col] = acc[i][j] + bias[col];
        }
    }
}

// ---------------- layer-1 projection GEMM v5 (R13-proven, unchanged) ----------------
#define LDW5 264
#define LDA5 72
#define LDB5 132
#define X5_BIAS 0
#define X5_WH   8448
#define X5_WL   (X5_WH  + 128 * LDW5 * 2)
#define X5_AH0  (X5_WL  + 128 * LDW5 * 2)
#define X5_AH1  (X5_AH0 + 128 * LDA5 * 2)
#define SMEM_X5 (X5_AH1 + 128 * LDA5 * 2)

__global__ __launch_bounds__(512, 1) void xgemm5(
    const __half* __restrict__ A,
    const float* __restrict__ Bf, const float* __restrict__ Bb,
    const float* __restrict__ biasf, const float* __restrict__ biasb,
    float* __restrict__ C)
{
    extern __shared__ char smem[];
    float* sBias = (float*)(smem + X5_BIAS);
    __half* sWh = (__half*)(smem + X5_WH);
    __half* sWl = (__half*)(smem + X5_WL);
    __half* sA[2] = { (__half*)(smem + X5_AH0), (__half*)(smem + X5_AH1) };

    const int tid = threadIdx.x;
    const int wid = tid >> 5;
    const int wm = wid & 3;
    const int wn = wid >> 2;

    const int bx = blockIdx.x;
    const int dir = bx / 3;
    const int ncol0 = (bx % 3) * 128;
    const float* W = dir ? Bb : Bf;
    const float* bias = dir ? biasb : biasf;
    float* Cb = C + (size_t)dir * BL * H3;

    for (int idx = tid; idx < 128 * 256; idx += 512) {
        int n = idx >> 8, k = idx & 255;
        float w = W[(size_t)(ncol0 + n) * H2 + k];
        __half hi = __float2half_rn(w);
        __half lo = __float2half_rn((w - __half2float(hi)) * 2048.0f);
        sWh[n * LDW5 + k] = hi;
        sWl[n * LDW5 + k] = lo;
    }
    for (int idx = tid; idx < 16 * 128; idx += 512) {
        int r = idx >> 7, c = idx & 127;
        sBias[r * LDB5 + c] = bias[ncol0 + c];
    }

    const int pr = tid >> 2;
    const int pc = (tid & 3) * 16;
    uint4 ph[2];

    #define FETCH_CHUNK(g) do { \
        int _it = (g) >> 2, _c = (g) & 3; \
        size_t _base = (((size_t)_it * 200 + blockIdx.y) * 128 + pr) * H2 + _c * 64 + pc; \
        ph[0] = *(const uint4*)(A + _base); ph[1] = *(const uint4*)(A + _base + 8); \
    } while (0)

    FETCH_CHUNK(0);
    __syncthreads();

    for (int it = 0; it < 8; ++it) {
        const size_t m0 = ((size_t)it * 200 + blockIdx.y) * 128;

        wmma::fragment<wmma::accumulator, 16, 16, 16, float> accH[2][2], accL[2][2];
        #pragma unroll
        for (int i = 0; i < 2; ++i)
            #pragma unroll
            for (int j = 0; j < 2; ++j) {
                wmma::load_matrix_sync(accH[i][j], sBias + wn * 32 + j * 16, LDB5, wmma::mem_row_major);
                wmma::fill_fragment(accL[i][j], 0.f);
            }

        for (int c = 0; c < 4; ++c) {
            const int g = it * 4 + c;
            const int buf = g & 1;

            __half* dA = sA[buf] + pr * LDA5 + pc;
            *(uint4*)(dA) = ph[0]; *(uint4*)(dA + 8) = ph[1];

            if (g + 1 < 32) FETCH_CHUNK(g + 1);
            __syncthreads();

            #pragma unroll
            for (int kk = 0; kk < 4; ++kk) {
                wmma::fragment<wmma::matrix_a, 16, 16, 16, __half, wmma::row_major> fa[2];
                wmma::fragment<wmma::matrix_b, 16, 16, 16, __half, wmma::col_major> fbh[2], fbl[2];
                #pragma unroll
                for (int i = 0; i < 2; ++i)
                    wmma::load_matrix_sync(fa[i], sA[buf] + (wm * 32 + i * 16) * LDA5 + kk * 16, LDA5);
                #pragma unroll
                for (int j = 0; j < 2; ++j) {
                    wmma::load_matrix_sync(fbh[j], sWh + (wn * 32 + j * 16) * LDW5 + c * 64 + kk * 16, LDW5);
                    wmma::load_matrix_sync(fbl[j], sWl + (wn * 32 + j * 16) * LDW5 + c * 64 + kk * 16, LDW5);
                }
                #pragma unroll
                for (int i = 0; i < 2; ++i)
                    #pragma unroll
                    for (int j = 0; j < 2; ++j) {
                        wmma::mma_sync(accH[i][j], fa[i], fbh[j], accH[i][j]);
                        wmma::mma_sync(accL[i][j], fa[i], fbl[j], accL[i][j]);
                    }
            }
        }

        const float inv = 1.0f / 2048.0f;
        #pragma unroll
        for (int i = 0; i < 2; ++i)
            #pragma unroll
            for (int j = 0; j < 2; ++j) {
                #pragma unroll
                for (int e = 0; e < accH[i][j].num_elements; ++e)
                    accH[i][j].x[e] = fmaf(accL[i][j].x[e], inv, accH[i][j].x[e]);
                wmma::store_matrix_sync(
                    Cb + (m0 + wm * 32 + i * 16) * H3 + ncol0 + wn * 32 + j * 16,
                    accH[i][j], H3, wmma::mem_row_major);
            }
    }
    #undef FETCH_CHUNK
}

// ---------------- tensor-core GRU: gate-blocked W, single mma phase, 2 syncs/step ----------------
// W layout: sWh[j][col'] with col' = g*128 + k (r: 0-127, z: 128-255, n: 256-383).
// lo-correction (2^11-scaled fp16) kept ONLY for the n gate (sWl, 128 cols).
// 12 mma warps (4 r, 4 z, 4 n — one of each per SMSP), all 16 warps do gates.
#define LDWP 392
#define LDWL 136
#define LDH  136
#define LDE  392
#define GOFF_WH  0
#define GOFF_WL  (GOFF_WH + 128 * LDWP * 2)      // 100352
#define GOFF_H   (GOFF_WL + 128 * LDWL * 2)      // 135168
#define GOFF_EPI (GOFF_H  + TB * LDH * 2)        // 139520
#define GOFF_BHH (GOFF_EPI + TB * LDE * 4)       // 164608
#define GOFF_BIH (GOFF_BHH + H3 * 4)             // 166144
#define GOFF_WIH (GOFF_BIH + H3 * 4)             // 167680
#define SMEM_GRUTC (GOFF_WIH + H3 * 2 * 4)       // 170752

template <int LAYER>
__global__ __launch_bounds__(512, 1) void gru_tc(
    const float* __restrict__ code,
    const float* __restrict__ xg,
    const float* __restrict__ Wih_f, const float* __restrict__ Wih_b,
    const float* __restrict__ Whh_f, const float* __restrict__ Whh_b,
    const float* __restrict__ bih_f, const float* __restrict__ bih_b,
    const float* __restrict__ bhh_f, const float* __restrict__ bhh_b,
    const float* __restrict__ Wf,                  // layer1: final head weights [1,256]
    float* __restrict__ gpart,                     // layer1: [2][BL][32] partial dots
    __half* __restrict__ hout)                     // layer0: h0 fp16
{
    extern __shared__ char smem[];
    __half* sWh = (__half*)(smem + GOFF_WH);
    __half* sWl = (__half*)(smem + GOFF_WL);
    __half* sH  = (__half*)(smem + GOFF_H);
    float* sEpi = (float*)(smem + GOFF_EPI);
    float* sBhh = (float*)(smem + GOFF_BHH);
    float* sBih = (float*)(smem + GOFF_BIH);
    float* sWih = (float*)(smem + GOFF_WIH);

    const int tid = threadIdx.x;
    const int dir = blockIdx.y;
    const int gb0 = blockIdx.x * TB;
    const float* Whh = dir ? Whh_b : Whh_f;
    const float* bhh = dir ? bhh_b : bhh_f;

    // Whh -> gate-blocked fp16 hi (all) + scaled lo (n gate only)
    for (int idx = tid; idx < H3 * HID; idx += 512) {
        int r = idx >> 7, j = idx & 127;            // r = g*128 + k (already gate-blocked)
        float w = Whh[r * HID + j];
        __half hi = __float2half_rn(w);
        sWh[j * LDWP + r] = hi;
        if (r >= 256)
            sWl[j * LDWL + (r - 256)] = __float2half_rn((w - __half2float(hi)) * 2048.0f);
    }
    for (int idx = tid; idx < H3; idx += 512) {
        sBhh[idx] = bhh[idx];
        if (LAYER == 0) {
            const float* Wih = dir ? Wih_b : Wih_f;
            const float* bih = dir ? bih_b : bih_f;
            sBih[idx] = bih[idx];
            sWih[idx * 2 + 0] = Wih[idx * 2 + 0];
            sWih[idx * 2 + 1] = Wih[idx * 2 + 1];
        }
    }
    for (int idx = tid; idx < TB * LDH; idx += 512)
        sH[idx] = __float2half_rn(0.f);
    __syncthreads();

    const int wid = tid >> 5, lane = tid & 31;
    const int b = wid;
    const int k0 = lane * 2;
    float h[4] = {0.f, 0.f, 0.f, 0.f};
    const float inv2048 = 1.0f / 2048.0f;
    const bool isN = (wid >= 8) && (wid < 12);
    const int colp = wid * 32;            // this warp's 32-col block within 384
    const int colpN = (wid - 8) * 32;     // within the n-only lo array

    float wf[4] = {0.f, 0.f, 0.f, 0.f};
    if (LAYER == 1) {
        #pragma unroll
        for (int i = 0; i < 4; ++i)
            wf[i] = __ldg(&Wf[dir * HID + (i >> 1) * 64 + k0 + (i & 1)]);
    }

    for (int t = 0; t < SEQ; ++t) {
        const int tt = dir ? (SEQ - 1 - t) : t;

        // ---- x-gate prefetch (overlaps mma) ----
        float xr[4], xz[4], xn[4];
        if (LAYER == 1) {
            const float* xp = xg + ((size_t)dir * BL + (size_t)(gb0 + b) * SEQ + tt) * H3;
            float2 v;
            v = *(const float2*)(xp + k0);            xr[0] = v.x; xr[1] = v.y;
            v = *(const float2*)(xp + 64 + k0);       xr[2] = v.x; xr[3] = v.y;
            v = *(const float2*)(xp + 128 + k0);      xz[0] = v.x; xz[1] = v.y;
            v = *(const float2*)(xp + 192 + k0);      xz[2] = v.x; xz[3] = v.y;
            v = *(const float2*)(xp + 256 + k0);      xn[0] = v.x; xn[1] = v.y;
            v = *(const float2*)(xp + 320 + k0);      xn[2] = v.x; xn[3] = v.y;
        } else {
            float c0 = __ldg(&code[(size_t)(gb0 + b) * NLIN + tt * 2 + 0]);
            float c1 = __ldg(&code[(size_t)(gb0 + b) * NLIN + tt * 2 + 1]);
            #pragma unroll
            for (int i = 0; i < 4; ++i) {
                int k = (i >> 1) * 64 + k0 + (i & 1);
                xr[i] = fmaf(c0, sWih[k * 2],           fmaf(c1, sWih[k * 2 + 1],           sBih[k]));
                xz[i] = fmaf(c0, sWih[(128 + k) * 2],   fmaf(c1, sWih[(128 + k) * 2 + 1],   sBih[128 + k]));
                xn[i] = fmaf(c0, sWih[(256 + k) * 2],   fmaf(c1, sWih[(256 + k) * 2 + 1],   sBih[256 + k]));
            }
        }

        // ---- single mma phase: all 384 gate columns ----
        if (wid < 12) {
            wmma::fragment<wmma::accumulator, 16, 16, 16, float> accH0, accH1, accL0, accL1;
            wmma::fill_fragment(accH0, 0.f);
            wmma::fill_fragment(accH1, 0.f);
            wmma::fill_fragment(accL0, 0.f);
            wmma::fill_fragment(accL1, 0.f);
            #pragma unroll
            for (int jf = 0; jf < 8; ++jf) {
                wmma::fragment<wmma::matrix_a, 16, 16, 16, __half, wmma::row_major> aF;
                wmma::fragment<wmma::matrix_b, 16, 16, 16, __half, wmma::row_major> bH0, bH1;
                wmma::load_matrix_sync(aF, sH + jf * 16, LDH);
                wmma::load_matrix_sync(bH0, sWh + (jf * 16) * LDWP + colp, LDWP);
                wmma::load_matrix_sync(bH1, sWh + (jf * 16) * LDWP + colp + 16, LDWP);
                wmma::mma_sync(accH0, aF, bH0, accH0);
                wmma::mma_sync(accH1, aF, bH1, accH1);
                if (isN) {
                    wmma::fragment<wmma::matrix_b, 16, 16, 16, __half, wmma::row_major> bL0, bL1;
                    wmma::load_matrix_sync(bL0, sWl + (jf * 16) * LDWL + colpN, LDWL);
                    wmma::load_matrix_sync(bL1, sWl + (jf * 16) * LDWL + colpN + 16, LDWL);
                    wmma::mma_sync(accL0, aF, bL0, accL0);
                    wmma::mma_sync(accL1, aF, bL1, accL1);
                }
            }
            if (isN) {
                #pragma unroll
                for (int e = 0; e < accH0.num_elements; ++e) {
                    accH0.x[e] = fmaf(accL0.x[e], inv2048, accH0.x[e]);
                    accH1.x[e] = fmaf(accL1.x[e], inv2048, accH1.x[e]);
                }
            }
            wmma::store_matrix_sync(sEpi + colp,      accH0, LDE, wmma::mem_row_major);
            wmma::store_matrix_sync(sEpi + colp + 16, accH1, LDE, wmma::mem_row_major);
        }
        __syncthreads();

        // ---- gates: all 4 k-values in one pass ----
        const float* eb = sEpi + b * LDE;
        #pragma unroll
        for (int i = 0; i < 4; ++i) {
            int k = (i >> 1) * 64 + k0 + (i & 1);
            float r = sigf(xr[i] + eb[k]       + sBhh[k]);
            float z = sigf(xz[i] + eb[128 + k] + sBhh[128 + k]);
            float n = tanhfast(xn[i] + r * (eb[256 + k] + sBhh[256 + k]));
            h[i] = (1.f - z) * n + z * h[i];
        }

        // ---- writeback ----
        const size_t row = (size_t)(gb0 + b) * SEQ + tt;
        __half2 p0 = __floats2half2_rn(h[0], h[1]);
        __half2 p1 = __floats2half2_rn(h[2], h[3]);
        *(__half2*)&sH[b * LDH + k0]      = p0;
        *(__half2*)&sH[b * LDH + 64 + k0] = p1;
        if (LAYER == 0) {
            *(__half2*)&hout[row * H2 + dir * HID + k0]      = p0;
            *(__half2*)&hout[row * H2 + dir * HID + 64 + k0] = p1;
        } else {
            float p = fmaf(h[0], wf[0], fmaf(h[1], wf[1], fmaf(h[2], wf[2], h[3] * wf[3])));
            gpart[((size_t)dir * BL + row) * 32 + lane] = p;
        }
        __syncthreads();
    }
}

// ---------------- final head: out = sigmoid(sum(partF)+sum(partB)+bf) ----------------
__global__ __launch_bounds__(256) void final2(
    const float* __restrict__ part, const float* __restrict__ bf,
    float* __restrict__ out)
{
    size_t i = (size_t)blockIdx.x * 256 + threadIdx.x;   // 0..BL-1
    const float4* p0 = (const float4*)(part + i * 32);
    const float4* p1 = (const float4*)(part + (size_t)BL * 32 + i * 32);
    float s = 0.f;
    #pragma unroll
    for (int q = 0; q < 8; ++q) { float4 v = p0[q]; s += v.x + v.y + v.z + v.w; }
    #pragma unroll
    for (int q = 0; q < 8; ++q) { float4 v = p1[q]; s += v.x + v.y + v.z + v.w; }
    out[i] = 1.f / (1.f + __expf(-(s + bf[0])));
}

// ---------------- launch ----------------
extern "C" void kernel_launch(void* const* d_in, const int* in_sizes, int n_in,
                              void* d_out, int out_size)
{
    const float* received = (const float*)d_in[0];
    const float* W_lin    = (const float*)d_in[1];
    const float* b_lin    = (const float*)d_in[2];
    const float* Wih0f = (const float*)d_in[3],  *Whh0f = (const float*)d_in[4];
    const float* bih0f = (const float*)d_in[5],  *bhh0f = (const float*)d_in[6];
    const float* Wih0b = (const float*)d_in[7],  *Whh0b = (const float*)d_in[8];
    const float* bih0b = (const float*)d_in[9],  *bhh0b = (const float*)d_in[10];
    const float* Wih1f = (const float*)d_in[11], *Whh1f = (const float*)d_in[12];
    const float* bih1f = (const float*)d_in[13], *bhh1f = (const float*)d_in[14];
    const float* Wih1b = (const float*)d_in[15], *Whh1b = (const float*)d_in[16];
    const float* bih1b = (const float*)d_in[17], *bhh1b = (const float*)d_in[18];
    const float* Wf    = (const float*)d_in[19], *bf    = (const float*)d_in[20];
    float* out = (float*)d_out;

    float *code, *xg1, *part;
    __half *h0h;
    cudaGetSymbolAddress((void**)&code, g_code);
    cudaGetSymbolAddress((void**)&h0h,  g_h0h);
    cudaGetSymbolAddress((void**)&xg1,  g_xg1);
    cudaGetSymbolAddress((void**)&part, g_part);

    cudaFuncSetAttribute(gru_tc<0>, cudaFuncAttributeMaxDynamicSharedMemorySize, (int)SMEM_GRUTC);
    cudaFuncSetAttribute(gru_tc<1>, cudaFuncAttributeMaxDynamicSharedMemorySize, (int)SMEM_GRUTC);
    cudaFuncSetAttribute(xgemm5, cudaFuncAttributeMaxDynamicSharedMemorySize, (int)SMEM_X5);

    // 1) dec_linear
    sgemm_nt<<<dim3(BATCH / 64, (NLIN + 63) / 64), 256>>>(
        received, W_lin, b_lin, code, BATCH, NLIN, NLIN);

    // 2) layer-0 bidirectional GRU (fp16 TC recurrence, single-phase) -> fp16 h0
    gru_tc<0><<<dim3(BATCH / TB, 2), 512, SMEM_GRUTC>>>(
        code, nullptr, Wih0f, Wih0b, Whh0f, Whh0b, bih0f, bih0b, bhh0f, bhh0b,
        nullptr, nullptr, h0h);

    // 3) layer-1 input projections (fp16 A single, fp16 W hi/lo scaled)
    xgemm5<<<dim3(6, 200), 512, SMEM_X5>>>(
        h0h, Wih1f, Wih1b, bih1f, bih1b, xg1);

    // 4) layer-1 bidirectional GRU with fused head partials
    gru_tc<1><<<dim3(BATCH / TB, 2), 512, SMEM_GRUTC>>>(
        nullptr, xg1, nullptr, nullptr, Whh1f, Whh1b, bih1f, bih1b, bhh1f, bhh1b,
        Wf, part, nullptr);

    // 5) output head reduction + sigmoid
    final2<<<BL / 256, 256>>>(part, bf, out);
}

// round 16
// speedup vs baseline: 2.5075x; 1.2659x over previous
#include <cuda_runtime.h>
#include <cuda_bf16.h>
#include <cuda_fp16.h>
#include <mma.h>
#include <math.h>
#include <stdint.h>

using namespace nvcuda;

#define BATCH 1024
#define SEQ   200
#define NLIN  400
#define HID   128
#define H2    256
#define H3    384
#define TB    16
#define BL    (BATCH * SEQ)

// ---------------- scratch (static device globals; no allocation) ----------------
__device__ float g_code[(size_t)BATCH * NLIN];
__device__ __half g_h0h[(size_t)BL * H2];        // h0 as fp16 (|h|<=1)
__device__ float g_xg1 [(size_t)2 * BL * H3];
__device__ float g_part[(size_t)2 * BL * 32];    // per-lane partial dots (fwd, bwd)

// tanh.approx.f32: baseline PTX (sm_75+), abs err ~2^-10.7 — below our fp16 noise floor
__device__ __forceinline__ float tanha(float x) {
    float y;
    asm("tanh.approx.f32 %0, %1;" : "=f"(y) : "f"(x));
    return y;
}
__device__ __forceinline__ float sig_a(float x) {
    return fmaf(0.5f, tanha(0.5f * x), 0.5f);
}

// ---------------- small SGEMM for dec_linear ----------------
__global__ __launch_bounds__(256) void sgemm_nt(
    const float* __restrict__ A, const float* __restrict__ B,
    const float* __restrict__ bias, float* __restrict__ C,
    int M, int N, int K)
{
    __shared__ float As[16][65];
    __shared__ float Bs[16][65];
    int tid = threadIdx.x;
    int tx = tid & 15, ty = tid >> 4;
    int bm0 = blockIdx.x * 64, bn0 = blockIdx.y * 64;
    int lrow = tid >> 2;
    int lc4  = (tid & 3) * 4;

    float acc[4][4] = {};

    for (int k0 = 0; k0 < K; k0 += 16) {
        float4 av = *(const float4*)(A + (size_t)(bm0 + lrow) * K + k0 + lc4);
        float4 bv = make_float4(0.f, 0.f, 0.f, 0.f);
        if (bn0 + lrow < N)
            bv = *(const float4*)(B + (size_t)(bn0 + lrow) * K + k0 + lc4);
        As[lc4 + 0][lrow] = av.x; As[lc4 + 1][lrow] = av.y;
        As[lc4 + 2][lrow] = av.z; As[lc4 + 3][lrow] = av.w;
        Bs[lc4 + 0][lrow] = bv.x; Bs[lc4 + 1][lrow] = bv.y;
        Bs[lc4 + 2][lrow] = bv.z; Bs[lc4 + 3][lrow] = bv.w;
        __syncthreads();
        #pragma unroll
        for (int kk = 0; kk < 16; ++kk) {
            float a[4], b[4];
            #pragma unroll
            for (int i = 0; i < 4; ++i) { a[i] = As[kk][ty * 4 + i]; b[i] = Bs[kk][tx * 4 + i]; }
            #pragma unroll
            for (int i = 0; i < 4; ++i)
                #pragma unroll
                for (int j = 0; j < 4; ++j)
                    acc[i][j] = fmaf(a[i], b[j], acc[i][j]);
        }
        __syncthreads();
    }

    #pragma unroll
    for (int i = 0; i < 4; ++i) {
        int row = bm0 + ty * 4 + i;
        #pragma unroll
        for (int j = 0; j < 4; ++j) {
            int col = bn0 + tx * 4 + j;
            if (col < N)
                C[(size_t)row * N + col] = acc[i][j] + bias[col];
        }
    }
}

// ---------------- layer-1 projection GEMM v6 ----------------
// fp16 A single-term; W hi + (2^11-scaled) lo — lo kept ONLY for the n-gate
// column block (bx%3==2, cols 256-383). r/z blocks are single-term.
#define LDW5 264
#define LDA5 72
#define LDB5 132
#define X5_BIAS 0
#define X5_WH   8448
#define X5_WL   (X5_WH  + 128 * LDW5 * 2)
#define X5_AH0  (X5_WL  + 128 * LDW5 * 2)
#define X5_AH1  (X5_AH0 + 128 * LDA5 * 2)
#define SMEM_X5 (X5_AH1 + 128 * LDA5 * 2)

__global__ __launch_bounds__(512, 1) void xgemm6(
    const __half* __restrict__ A,
    const float* __restrict__ Bf, const float* __restrict__ Bb,
    const float* __restrict__ biasf, const float* __restrict__ biasb,
    float* __restrict__ C)
{
    extern __shared__ char smem[];
    float* sBias = (float*)(smem + X5_BIAS);
    __half* sWh = (__half*)(smem + X5_WH);
    __half* sWl = (__half*)(smem + X5_WL);
    __half* sA[2] = { (__half*)(smem + X5_AH0), (__half*)(smem + X5_AH1) };

    const int tid = threadIdx.x;
    const int wid = tid >> 5;
    const int wm = wid & 3;
    const int wn = wid >> 2;

    const int bx = blockIdx.x;
    const int dir = bx / 3;
    const int colt = bx % 3;
    const int ncol0 = colt * 128;
    const bool hasLo = (colt == 2);         // n-gate columns need the lo term
    const float* W = dir ? Bb : Bf;
    const float* bias = dir ? biasb : biasf;
    float* Cb = C + (size_t)dir * BL * H3;

    for (int idx = tid; idx < 128 * 256; idx += 512) {
        int n = idx >> 8, k = idx & 255;
        float w = W[(size_t)(ncol0 + n) * H2 + k];
        __half hi = __float2half_rn(w);
        sWh[n * LDW5 + k] = hi;
        if (hasLo)
            sWl[n * LDW5 + k] = __float2half_rn((w - __half2float(hi)) * 2048.0f);
    }
    for (int idx = tid; idx < 16 * 128; idx += 512) {
        int r = idx >> 7, c = idx & 127;
        sBias[r * LDB5 + c] = bias[ncol0 + c];
    }

    const int pr = tid >> 2;
    const int pc = (tid & 3) * 16;
    uint4 ph[2];

    #define FETCH_CHUNK(g) do { \
        int _it = (g) >> 2, _c = (g) & 3; \
        size_t _base = (((size_t)_it * 200 + blockIdx.y) * 128 + pr) * H2 + _c * 64 + pc; \
        ph[0] = *(const uint4*)(A + _base); ph[1] = *(const uint4*)(A + _base + 8); \
    } while (0)

    FETCH_CHUNK(0);
    __syncthreads();

    for (int it = 0; it < 8; ++it) {
        const size_t m0 = ((size_t)it * 200 + blockIdx.y) * 128;

        wmma::fragment<wmma::accumulator, 16, 16, 16, float> accH[2][2], accL[2][2];
        #pragma unroll
        for (int i = 0; i < 2; ++i)
            #pragma unroll
            for (int j = 0; j < 2; ++j) {
                wmma::load_matrix_sync(accH[i][j], sBias + wn * 32 + j * 16, LDB5, wmma::mem_row_major);
                wmma::fill_fragment(accL[i][j], 0.f);
            }

        for (int c = 0; c < 4; ++c) {
            const int g = it * 4 + c;
            const int buf = g & 1;

            __half* dA = sA[buf] + pr * LDA5 + pc;
            *(uint4*)(dA) = ph[0]; *(uint4*)(dA + 8) = ph[1];

            if (g + 1 < 32) FETCH_CHUNK(g + 1);
            __syncthreads();

            #pragma unroll
            for (int kk = 0; kk < 4; ++kk) {
                wmma::fragment<wmma::matrix_a, 16, 16, 16, __half, wmma::row_major> fa[2];
                wmma::fragment<wmma::matrix_b, 16, 16, 16, __half, wmma::col_major> fbh[2];
                #pragma unroll
                for (int i = 0; i < 2; ++i)
                    wmma::load_matrix_sync(fa[i], sA[buf] + (wm * 32 + i * 16) * LDA5 + kk * 16, LDA5);
                #pragma unroll
                for (int j = 0; j < 2; ++j)
                    wmma::load_matrix_sync(fbh[j], sWh + (wn * 32 + j * 16) * LDW5 + c * 64 + kk * 16, LDW5);
                #pragma unroll
                for (int i = 0; i < 2; ++i)
                    #pragma unroll
                    for (int j = 0; j < 2; ++j)
                        wmma::mma_sync(accH[i][j], fa[i], fbh[j], accH[i][j]);
                if (hasLo) {
                    wmma::fragment<wmma::matrix_b, 16, 16, 16, __half, wmma::col_major> fbl[2];
                    #pragma unroll
                    for (int j = 0; j < 2; ++j)
                        wmma::load_matrix_sync(fbl[j], sWl + (wn * 32 + j * 16) * LDW5 + c * 64 + kk * 16, LDW5);
                    #pragma unroll
                    for (int i = 0; i < 2; ++i)
                        #pragma unroll
                        for (int j = 0; j < 2; ++j)
                            wmma::mma_sync(accL[i][j], fa[i], fbl[j], accL[i][j]);
                }
            }
        }

        const float inv = 1.0f / 2048.0f;
        #pragma unroll
        for (int i = 0; i < 2; ++i)
            #pragma unroll
            for (int j = 0; j < 2; ++j) {
                if (hasLo) {
                    #pragma unroll
                    for (int e = 0; e < accH[i][j].num_elements; ++e)
                        accH[i][j].x[e] = fmaf(accL[i][j].x[e], inv, accH[i][j].x[e]);
                }
                wmma::store_matrix_sync(
                    Cb + (m0 + wm * 32 + i * 16) * H3 + ncol0 + wn * 32 + j * 16,
                    accH[i][j], H3, wmma::mem_row_major);
            }
    }
    #undef FETCH_CHUNK
}

// ---------------- tensor-core GRU: gate-blocked W, single mma phase, approx gates ----------------
#define LDWP 392
#define LDWL 136
#define LDH  136
#define LDE  392
#define GOFF_WH  0
#define GOFF_WL  (GOFF_WH + 128 * LDWP * 2)      // 100352
#define GOFF_H   (GOFF_WL + 128 * LDWL * 2)      // 135168
#define GOFF_EPI (GOFF_H  + TB * LDH * 2)        // 139520
#define GOFF_BHH (GOFF_EPI + TB * LDE * 4)       // 164608
#define GOFF_BIH (GOFF_BHH + H3 * 4)             // 166144
#define GOFF_WIH (GOFF_BIH + H3 * 4)             // 167680
#define SMEM_GRUTC (GOFF_WIH + H3 * 2 * 4)       // 170752

template <int LAYER>
__global__ __launch_bounds__(512, 1) void gru_tc(
    const float* __restrict__ code,
    const float* __restrict__ xg,
    const float* __restrict__ Wih_f, const float* __restrict__ Wih_b,
    const float* __restrict__ Whh_f, const float* __restrict__ Whh_b,
    const float* __restrict__ bih_f, const float* __restrict__ bih_b,
    const float* __restrict__ bhh_f, const float* __restrict__ bhh_b,
    const float* __restrict__ Wf,
    float* __restrict__ gpart,
    __half* __restrict__ hout)
{
    extern __shared__ char smem[];
    __half* sWh = (__half*)(smem + GOFF_WH);
    __half* sWl = (__half*)(smem + GOFF_WL);
    __half* sH  = (__half*)(smem + GOFF_H);
    float* sEpi = (float*)(smem + GOFF_EPI);
    float* sBhh = (float*)(smem + GOFF_BHH);
    float* sBih = (float*)(smem + GOFF_BIH);
    float* sWih = (float*)(smem + GOFF_WIH);

    const int tid = threadIdx.x;
    const int dir = blockIdx.y;
    const int gb0 = blockIdx.x * TB;
    const float* Whh = dir ? Whh_b : Whh_f;
    const float* bhh = dir ? bhh_b : bhh_f;

    for (int idx = tid; idx < H3 * HID; idx += 512) {
        int r = idx >> 7, j = idx & 127;
        float w = Whh[r * HID + j];
        __half hi = __float2half_rn(w);
        sWh[j * LDWP + r] = hi;
        if (r >= 256)
            sWl[j * LDWL + (r - 256)] = __float2half_rn((w - __half2float(hi)) * 2048.0f);
    }
    for (int idx = tid; idx < H3; idx += 512) {
        sBhh[idx] = bhh[idx];
        if (LAYER == 0) {
            const float* Wih = dir ? Wih_b : Wih_f;
            const float* bih = dir ? bih_b : bih_f;
            sBih[idx] = bih[idx];
            sWih[idx * 2 + 0] = Wih[idx * 2 + 0];
            sWih[idx * 2 + 1] = Wih[idx * 2 + 1];
        }
    }
    for (int idx = tid; idx < TB * LDH; idx += 512)
        sH[idx] = __float2half_rn(0.f);
    __syncthreads();

    const int wid = tid >> 5, lane = tid & 31;
    const int b = wid;
    const int k0 = lane * 2;
    float h[4] = {0.f, 0.f, 0.f, 0.f};
    const float inv2048 = 1.0f / 2048.0f;
    const bool isN = (wid >= 8) && (wid < 12);
    const int colp = wid * 32;
    const int colpN = (wid - 8) * 32;

    float wf[4] = {0.f, 0.f, 0.f, 0.f};
    if (LAYER == 1) {
        #pragma unroll
        for (int i = 0; i < 4; ++i)
            wf[i] = __ldg(&Wf[dir * HID + (i >> 1) * 64 + k0 + (i & 1)]);
    }

    for (int t = 0; t < SEQ; ++t) {
        const int tt = dir ? (SEQ - 1 - t) : t;

        float xr[4], xz[4], xn[4];
        if (LAYER == 1) {
            const float* xp = xg + ((size_t)dir * BL + (size_t)(gb0 + b) * SEQ + tt) * H3;
            float2 v;
            v = *(const float2*)(xp + k0);            xr[0] = v.x; xr[1] = v.y;
            v = *(const float2*)(xp + 64 + k0);       xr[2] = v.x; xr[3] = v.y;
            v = *(const float2*)(xp + 128 + k0);      xz[0] = v.x; xz[1] = v.y;
            v = *(const float2*)(xp + 192 + k0);      xz[2] = v.x; xz[3] = v.y;
            v = *(const float2*)(xp + 256 + k0);      xn[0] = v.x; xn[1] = v.y;
            v = *(const float2*)(xp + 320 + k0);      xn[2] = v.x; xn[3] = v.y;
        } else {
            float c0 = __ldg(&code[(size_t)(gb0 + b) * NLIN + tt * 2 + 0]);
            float c1 = __ldg(&code[(size_t)(gb0 + b) * NLIN + tt * 2 + 1]);
            #pragma unroll
            for (int i = 0; i < 4; ++i) {
                int k = (i >> 1) * 64 + k0 + (i & 1);
                xr[i] = fmaf(c0, sWih[k * 2],           fmaf(c1, sWih[k * 2 + 1],           sBih[k]));
                xz[i] = fmaf(c0, sWih[(128 + k) * 2],   fmaf(c1, sWih[(128 + k) * 2 + 1],   sBih[128 + k]));
                xn[i] = fmaf(c0, sWih[(256 + k) * 2],   fmaf(c1, sWih[(256 + k) * 2 + 1],   sBih[256 + k]));
            }
        }

        // ---- single mma phase: all 384 gate columns ----
        if (wid < 12) {
            wmma::fragment<wmma::accumulator, 16, 16, 16, float> accH0, accH1, accL0, accL1;
            wmma::fill_fragment(accH0, 0.f);
            wmma::fill_fragment(accH1, 0.f);
            wmma::fill_fragment(accL0, 0.f);
            wmma::fill_fragment(accL1, 0.f);
            #pragma unroll
            for (int jf = 0; jf < 8; ++jf) {
                wmma::fragment<wmma::matrix_a, 16, 16, 16, __half, wmma::row_major> aF;
                wmma::fragment<wmma::matrix_b, 16, 16, 16, __half, wmma::row_major> bH0, bH1;
                wmma::load_matrix_sync(aF, sH + jf * 16, LDH);
                wmma::load_matrix_sync(bH0, sWh + (jf * 16) * LDWP + colp, LDWP);
                wmma::load_matrix_sync(bH1, sWh + (jf * 16) * LDWP + colp + 16, LDWP);
                wmma::mma_sync(accH0, aF, bH0, accH0);
                wmma::mma_sync(accH1, aF, bH1, accH1);
                if (isN) {
                    wmma::fragment<wmma::matrix_b, 16, 16, 16, __half, wmma::row_major> bL0, bL1;
                    wmma::load_matrix_sync(bL0, sWl + (jf * 16) * LDWL + colpN, LDWL);
                    wmma::load_matrix_sync(bL1, sWl + (jf * 16) * LDWL + colpN + 16, LDWL);
                    wmma::mma_sync(accL0, aF, bL0, accL0);
                    wmma::mma_sync(accL1, aF, bL1, accL1);
                }
            }
            if (isN) {
                #pragma unroll
                for (int e = 0; e < accH0.num_elements; ++e) {
                    accH0.x[e] = fmaf(accL0.x[e], inv2048, accH0.x[e]);
                    accH1.x[e] = fmaf(accL1.x[e], inv2048, accH1.x[e]);
                }
            }
            wmma::store_matrix_sync(sEpi + colp,      accH0, LDE, wmma::mem_row_major);
            wmma::store_matrix_sync(sEpi + colp + 16, accH1, LDE, wmma::mem_row_major);
        }
        __syncthreads();

        // ---- gates (tanh.approx-based, no divisions) ----
        const float* eb = sEpi + b * LDE;
        #pragma unroll
        for (int i = 0; i < 4; ++i) {
            int k = (i >> 1) * 64 + k0 + (i & 1);
            float r = sig_a(xr[i] + eb[k]       + sBhh[k]);
            float z = sig_a(xz[i] + eb[128 + k] + sBhh[128 + k]);
            float n = tanha(xn[i] + r * (eb[256 + k] + sBhh[256 + k]));
            h[i] = (1.f - z) * n + z * h[i];
        }

        // ---- writeback ----
        const size_t row = (size_t)(gb0 + b) * SEQ + tt;
        __half2 p0 = __floats2half2_rn(h[0], h[1]);
        __half2 p1 = __floats2half2_rn(h[2], h[3]);
        *(__half2*)&sH[b * LDH + k0]      = p0;
        *(__half2*)&sH[b * LDH + 64 + k0] = p1;
        if (LAYER == 0) {
            *(__half2*)&hout[row * H2 + dir * HID + k0]      = p0;
            *(__half2*)&hout[row * H2 + dir * HID + 64 + k0] = p1;
        } else {
            float p = fmaf(h[0], wf[0], fmaf(h[1], wf[1], fmaf(h[2], wf[2], h[3] * wf[3])));
            gpart[((size_t)dir * BL + row) * 32 + lane] = p;
        }
        __syncthreads();
    }
}

// ---------------- final head: out = sigmoid(sum(partF)+sum(partB)+bf) ----------------
__global__ __launch_bounds__(256) void final2(
    const float* __restrict__ part, const float* __restrict__ bf,
    float* __restrict__ out)
{
    size_t i = (size_t)blockIdx.x * 256 + threadIdx.x;
    const float4* p0 = (const float4*)(part + i * 32);
    const float4* p1 = (const float4*)(part + (size_t)BL * 32 + i * 32);
    float s = 0.f;
    #pragma unroll
    for (int q = 0; q < 8; ++q) { float4 v = p0[q]; s += v.x + v.y + v.z + v.w; }
    #pragma unroll
    for (int q = 0; q < 8; ++q) { float4 v = p1[q]; s += v.x + v.y + v.z + v.w; }
    out[i] = 1.f / (1.f + __expf(-(s + bf[0])));
}

// ---------------- launch ----------------
extern "C" void kernel_launch(void* const* d_in, const int* in_sizes, int n_in,
                              void* d_out, int out_size)
{
    const float* received = (const float*)d_in[0];
    const float* W_lin    = (const float*)d_in[1];
    const float* b_lin    = (const float*)d_in[2];
    const float* Wih0f = (const float*)d_in[3],  *Whh0f = (const float*)d_in[4];
    const float* bih0f = (const float*)d_in[5],  *bhh0f = (const float*)d_in[6];
    const float* Wih0b = (const float*)d_in[7],  *Whh0b = (const float*)d_in[8];
    const float* bih0b = (const float*)d_in[9],  *bhh0b = (const float*)d_in[10];
    const float* Wih1f = (const float*)d_in[11], *Whh1f = (const float*)d_in[12];
    const float* bih1f = (const float*)d_in[13], *bhh1f = (const float*)d_in[14];
    const float* Wih1b = (const float*)d_in[15], *Whh1b = (const float*)d_in[16];
    const float* bih1b = (const float*)d_in[17], *bhh1b = (const float*)d_in[18];
    const float* Wf    = (const float*)d_in[19], *bf    = (const float*)d_in[20];
    float* out = (float*)d_out;

    float *code, *xg1, *part;
    __half *h0h;
    cudaGetSymbolAddress((void**)&code, g_code);
    cudaGetSymbolAddress((void**)&h0h,  g_h0h);
    cudaGetSymbolAddress((void**)&xg1,  g_xg1);
    cudaGetSymbolAddress((void**)&part, g_part);

    cudaFuncSetAttribute(gru_tc<0>, cudaFuncAttributeMaxDynamicSharedMemorySize, (int)SMEM_GRUTC);
    cudaFuncSetAttribute(gru_tc<1>, cudaFuncAttributeMaxDynamicSharedMemorySize, (int)SMEM_GRUTC);
    cudaFuncSetAttribute(xgemm6, cudaFuncAttributeMaxDynamicSharedMemorySize, (int)SMEM_X5);

    // 1) dec_linear
    sgemm_nt<<<dim3(BATCH / 64, (NLIN + 63) / 64), 256>>>(
        received, W_lin, b_lin, code, BATCH, NLIN, NLIN);

    // 2) layer-0 bidirectional GRU -> fp16 h0
    gru_tc<0><<<dim3(BATCH / TB, 2), 512, SMEM_GRUTC>>>(
        code, nullptr, Wih0f, Wih0b, Whh0f, Whh0b, bih0f, bih0b, bhh0f, bhh0b,
        nullptr, nullptr, h0h);

    // 3) layer-1 input projections (lo-term only for n-gate block)
    xgemm6<<<dim3(6, 200), 512, SMEM_X5>>>(
        h0h, Wih1f, Wih1b, bih1f, bih1b, xg1);

    // 4) layer-1 bidirectional GRU with fused head partials
    gru_tc<1><<<dim3(BATCH / TB, 2), 512, SMEM_GRUTC>>>(
        nullptr, xg1, nullptr, nullptr, Whh1f, Whh1b, bih1f, bih1b, bhh1f, bhh1b,
        Wf, part, nullptr);

    // 5) output head reduction + sigmoid
    final2<<<BL / 256, 256>>>(part, bf, out);
}

// round 17
// speedup vs baseline: 3.1596x; 1.2601x over previous
#include <cuda_runtime.h>
#include <cuda_bf16.h>
#include <cuda_fp16.h>
#include <mma.h>
#include <math.h>
#include <stdint.h>

using namespace nvcuda;

#define BATCH 1024
#define SEQ   200
#define NLIN  400
#define HID   128
#define H2    256
#define H3    384
#define TB    16
#define BL    (BATCH * SEQ)

// ---------------- scratch (static device globals; no allocation) ----------------
__device__ float g_code[(size_t)BATCH * NLIN];
__device__ __half g_h0h[(size_t)BL * H2];        // h0 as fp16 (|h|<=1)
__device__ __half g_xg1h[(size_t)2 * BL * H3];   // layer-1 input gates, fp16 (314 MB)
__device__ float g_part[(size_t)2 * BL * 32];    // per-lane partial dots (fwd, bwd)

// tanh.approx.f32: baseline PTX (sm_75+), abs err ~2^-10.7 — below fp16 noise floor
__device__ __forceinline__ float tanha(float x) {
    float y;
    asm("tanh.approx.f32 %0, %1;" : "=f"(y) : "f"(x));
    return y;
}
__device__ __forceinline__ float sig_a(float x) {
    return fmaf(0.5f, tanha(0.5f * x), 0.5f);
}

// ---------------- small SGEMM for dec_linear ----------------
__global__ __launch_bounds__(256) void sgemm_nt(
    const float* __restrict__ A, const float* __restrict__ B,
    const float* __restrict__ bias, float* __restrict__ C,
    int M, int N, int K)
{
    __shared__ float As[16][65];
    __shared__ float Bs[16][65];
    int tid = threadIdx.x;
    int tx = tid & 15, ty = tid >> 4;
    int bm0 = blockIdx.x * 64, bn0 = blockIdx.y * 64;
    int lrow = tid >> 2;
    int lc4  = (tid & 3) * 4;

    float acc[4][4] = {};

    for (int k0 = 0; k0 < K; k0 += 16) {
        float4 av = *(const float4*)(A + (size_t)(bm0 + lrow) * K + k0 + lc4);
        float4 bv = make_float4(0.f, 0.f, 0.f, 0.f);
        if (bn0 + lrow < N)
            bv = *(const float4*)(B + (size_t)(bn0 + lrow) * K + k0 + lc4);
        As[lc4 + 0][lrow] = av.x; As[lc4 + 1][lrow] = av.y;
        As[lc4 + 2][lrow] = av.z; As[lc4 + 3][lrow] = av.w;
        Bs[lc4 + 0][lrow] = bv.x; Bs[lc4 + 1][lrow] = bv.y;
        Bs[lc4 + 2][lrow] = bv.z; Bs[lc4 + 3][lrow] = bv.w;
        __syncthreads();
        #pragma unroll
        for (int kk = 0; kk < 16; ++kk) {
            float a[4], b[4];
            #pragma unroll
            for (int i = 0; i < 4; ++i) { a[i] = As[kk][ty * 4 + i]; b[i] = Bs[kk][tx * 4 + i]; }
            #pragma unroll
            for (int i = 0; i < 4; ++i)
                #pragma unroll
                for (int j = 0; j < 4; ++j)
                    acc[i][j] = fmaf(a[i], b[j], acc[i][j]);
        }
        __syncthreads();
    }

    #pragma unroll
    for (int i = 0; i < 4; ++i) {
        int row = bm0 + ty * 4 + i;
        #pragma unroll
        for (int j = 0; j < 4; ++j) {
            int col = bn0 + tx * 4 + j;
            if (col < N)
                C[(size_t)row * N + col] = acc[i][j] + bias[col];
        }
    }
}

// ---------------- layer-1 projection GEMM v7: single-term fp16, fp16 output ----------------
// C[2][BL][384] (__half) = h0[BL][256] @ Wih1{f,b}^T + bias.
// grid (6,200), 512 thr = 16 warps (4m x 4n), warp tile 32x32, K-chunk 64 double-buffered.
#define LDW7 264
#define LDA7 72
#define LDB7 132
#define LDE7 132
#define X7_BIAS 0
#define X7_WH   8448
#define X7_A0   (X7_WH + 128 * LDW7 * 2)
#define X7_A1   (X7_A0 + 128 * LDA7 * 2)
#define X7_EPI  (X7_A1 + 128 * LDA7 * 2)
#define SMEM_X7 (X7_EPI + 128 * LDE7 * 4)      // 180480

__global__ __launch_bounds__(512, 1) void xgemm7(
    const __half* __restrict__ A,
    const float* __restrict__ Bf, const float* __restrict__ Bb,
    const float* __restrict__ biasf, const float* __restrict__ biasb,
    __half* __restrict__ C)
{
    extern __shared__ char smem[];
    float* sBias = (float*)(smem + X7_BIAS);
    __half* sWh = (__half*)(smem + X7_WH);
    __half* sA[2] = { (__half*)(smem + X7_A0), (__half*)(smem + X7_A1) };
    float* sEpi = (float*)(smem + X7_EPI);

    const int tid = threadIdx.x;
    const int wid = tid >> 5;
    const int wm = wid & 3;
    const int wn = wid >> 2;

    const int bx = blockIdx.x;
    const int dir = bx / 3;
    const int ncol0 = (bx % 3) * 128;
    const float* W = dir ? Bb : Bf;
    const float* bias = dir ? biasb : biasf;
    __half* Cb = C + (size_t)dir * BL * H3;

    for (int idx = tid; idx < 128 * 256; idx += 512) {
        int n = idx >> 8, k = idx & 255;
        sWh[n * LDW7 + k] = __float2half_rn(W[(size_t)(ncol0 + n) * H2 + k]);
    }
    for (int idx = tid; idx < 16 * 128; idx += 512) {
        int r = idx >> 7, c = idx & 127;
        sBias[r * LDB7 + c] = bias[ncol0 + c];
    }

    const int pr = tid >> 2;
    const int pc = (tid & 3) * 16;
    uint4 ph[2];

    #define FETCH_CHUNK(g) do { \
        int _it = (g) >> 2, _c = (g) & 3; \
        size_t _base = (((size_t)_it * 200 + blockIdx.y) * 128 + pr) * H2 + _c * 64 + pc; \
        ph[0] = *(const uint4*)(A + _base); ph[1] = *(const uint4*)(A + _base + 8); \
    } while (0)

    FETCH_CHUNK(0);
    __syncthreads();

    for (int it = 0; it < 8; ++it) {
        const size_t m0 = ((size_t)it * 200 + blockIdx.y) * 128;

        wmma::fragment<wmma::accumulator, 16, 16, 16, float> acc[2][2];
        #pragma unroll
        for (int i = 0; i < 2; ++i)
            #pragma unroll
            for (int j = 0; j < 2; ++j)
                wmma::load_matrix_sync(acc[i][j], sBias + wn * 32 + j * 16, LDB7, wmma::mem_row_major);

        for (int c = 0; c < 4; ++c) {
            const int g = it * 4 + c;
            const int buf = g & 1;

            __half* dA = sA[buf] + pr * LDA7 + pc;
            *(uint4*)(dA) = ph[0]; *(uint4*)(dA + 8) = ph[1];

            if (g + 1 < 32) FETCH_CHUNK(g + 1);
            __syncthreads();

            #pragma unroll
            for (int kk = 0; kk < 4; ++kk) {
                wmma::fragment<wmma::matrix_a, 16, 16, 16, __half, wmma::row_major> fa[2];
                wmma::fragment<wmma::matrix_b, 16, 16, 16, __half, wmma::col_major> fb[2];
                #pragma unroll
                for (int i = 0; i < 2; ++i)
                    wmma::load_matrix_sync(fa[i], sA[buf] + (wm * 32 + i * 16) * LDA7 + kk * 16, LDA7);
                #pragma unroll
                for (int j = 0; j < 2; ++j)
                    wmma::load_matrix_sync(fb[j], sWh + (wn * 32 + j * 16) * LDW7 + c * 64 + kk * 16, LDW7);
                #pragma unroll
                for (int i = 0; i < 2; ++i)
                    #pragma unroll
                    for (int j = 0; j < 2; ++j)
                        wmma::mma_sync(acc[i][j], fa[i], fb[j], acc[i][j]);
            }
        }

        // epilogue: frags -> smem -> fp16 global
        #pragma unroll
        for (int i = 0; i < 2; ++i)
            #pragma unroll
            for (int j = 0; j < 2; ++j)
                wmma::store_matrix_sync(sEpi + (wm * 32 + i * 16) * LDE7 + wn * 32 + j * 16,
                                        acc[i][j], LDE7, wmma::mem_row_major);
        __syncthreads();
        for (int idx = tid; idx < 128 * 16; idx += 512) {
            int r = idx >> 4, c8 = (idx & 15) * 8;
            const float* e = sEpi + r * LDE7 + c8;
            __half2 o[4];
            o[0] = __floats2half2_rn(e[0], e[1]);
            o[1] = __floats2half2_rn(e[2], e[3]);
            o[2] = __floats2half2_rn(e[4], e[5]);
            o[3] = __floats2half2_rn(e[6], e[7]);
            *(uint4*)(Cb + (m0 + r) * H3 + ncol0 + c8) = *(uint4*)o;
        }
        __syncthreads();   // sEpi free before next tile's frag store
    }
    #undef FETCH_CHUNK
}

// ---------------- tensor-core GRU: gate-blocked single-term fp16 W, approx gates ----------------
#define LDWP 392
#define LDH  136
#define LDE  392
#define GOFF_WH  0
#define GOFF_H   (GOFF_WH + 128 * LDWP * 2)      // 100352
#define GOFF_EPI (GOFF_H  + TB * LDH * 2)        // 104704
#define GOFF_BHH (GOFF_EPI + TB * LDE * 4)       // 129792
#define GOFF_BIH (GOFF_BHH + H3 * 4)             // 131328
#define GOFF_WIH (GOFF_BIH + H3 * 4)             // 132864
#define SMEM_GRUTC (GOFF_WIH + H3 * 2 * 4)       // 135936

template <int LAYER>
__global__ __launch_bounds__(512, 1) void gru_tc(
    const float* __restrict__ code,
    const __half* __restrict__ xg,
    const float* __restrict__ Wih_f, const float* __restrict__ Wih_b,
    const float* __restrict__ Whh_f, const float* __restrict__ Whh_b,
    const float* __restrict__ bih_f, const float* __restrict__ bih_b,
    const float* __restrict__ bhh_f, const float* __restrict__ bhh_b,
    const float* __restrict__ Wf,
    float* __restrict__ gpart,
    __half* __restrict__ hout)
{
    extern __shared__ char smem[];
    __half* sWh = (__half*)(smem + GOFF_WH);
    __half* sH  = (__half*)(smem + GOFF_H);
    float* sEpi = (float*)(smem + GOFF_EPI);
    float* sBhh = (float*)(smem + GOFF_BHH);
    float* sBih = (float*)(smem + GOFF_BIH);
    float* sWih = (float*)(smem + GOFF_WIH);

    const int tid = threadIdx.x;
    const int dir = blockIdx.y;
    const int gb0 = blockIdx.x * TB;
    const float* Whh = dir ? Whh_b : Whh_f;
    const float* bhh = dir ? bhh_b : bhh_f;

    // Whh -> gate-blocked fp16 (single term): sWh[j][g*128+k]
    for (int idx = tid; idx < H3 * HID; idx += 512) {
        int r = idx >> 7, j = idx & 127;
        sWh[j * LDWP + r] = __float2half_rn(Whh[r * HID + j]);
    }
    for (int idx = tid; idx < H3; idx += 512) {
        sBhh[idx] = bhh[idx];
        if (LAYER == 0) {
            const float* Wih = dir ? Wih_b : Wih_f;
            const float* bih = dir ? bih_b : bih_f;
            sBih[idx] = bih[idx];
            sWih[idx * 2 + 0] = Wih[idx * 2 + 0];
            sWih[idx * 2 + 1] = Wih[idx * 2 + 1];
        }
    }
    for (int idx = tid; idx < TB * LDH; idx += 512)
        sH[idx] = __float2half_rn(0.f);
    __syncthreads();

    const int wid = tid >> 5, lane = tid & 31;
    const int b = wid;
    const int k0 = lane * 2;
    float h[4] = {0.f, 0.f, 0.f, 0.f};
    const int colp = wid * 32;

    float wf[4] = {0.f, 0.f, 0.f, 0.f};
    if (LAYER == 1) {
        #pragma unroll
        for (int i = 0; i < 4; ++i)
            wf[i] = __ldg(&Wf[dir * HID + (i >> 1) * 64 + k0 + (i & 1)]);
    }

    for (int t = 0; t < SEQ; ++t) {
        const int tt = dir ? (SEQ - 1 - t) : t;

        // ---- x-gate prefetch (overlaps mma) ----
        float xr[4], xz[4], xn[4];
        if (LAYER == 1) {
            const __half* xp = xg + ((size_t)dir * BL + (size_t)(gb0 + b) * SEQ + tt) * H3;
            float2 f;
            f = __half22float2(*(const __half2*)(xp + k0));        xr[0] = f.x; xr[1] = f.y;
            f = __half22float2(*(const __half2*)(xp + 64 + k0));   xr[2] = f.x; xr[3] = f.y;
            f = __half22float2(*(const __half2*)(xp + 128 + k0));  xz[0] = f.x; xz[1] = f.y;
            f = __half22float2(*(const __half2*)(xp + 192 + k0));  xz[2] = f.x; xz[3] = f.y;
            f = __half22float2(*(const __half2*)(xp + 256 + k0));  xn[0] = f.x; xn[1] = f.y;
            f = __half22float2(*(const __half2*)(xp + 320 + k0));  xn[2] = f.x; xn[3] = f.y;
        } else {
            float c0 = __ldg(&code[(size_t)(gb0 + b) * NLIN + tt * 2 + 0]);
            float c1 = __ldg(&code[(size_t)(gb0 + b) * NLIN + tt * 2 + 1]);
            #pragma unroll
            for (int i = 0; i < 4; ++i) {
                int k = (i >> 1) * 64 + k0 + (i & 1);
                xr[i] = fmaf(c0, sWih[k * 2],           fmaf(c1, sWih[k * 2 + 1],           sBih[k]));
                xz[i] = fmaf(c0, sWih[(128 + k) * 2],   fmaf(c1, sWih[(128 + k) * 2 + 1],   sBih[128 + k]));
                xn[i] = fmaf(c0, sWih[(256 + k) * 2],   fmaf(c1, sWih[(256 + k) * 2 + 1],   sBih[256 + k]));
            }
        }

        // ---- single mma phase: all 384 gate columns, balanced across 12 warps ----
        if (wid < 12) {
            wmma::fragment<wmma::accumulator, 16, 16, 16, float> acc0, acc1;
            wmma::fill_fragment(acc0, 0.f);
            wmma::fill_fragment(acc1, 0.f);
            #pragma unroll
            for (int jf = 0; jf < 8; ++jf) {
                wmma::fragment<wmma::matrix_a, 16, 16, 16, __half, wmma::row_major> aF;
                wmma::fragment<wmma::matrix_b, 16, 16, 16, __half, wmma::row_major> b0, b1;
                wmma::load_matrix_sync(aF, sH + jf * 16, LDH);
                wmma::load_matrix_sync(b0, sWh + (jf * 16) * LDWP + colp, LDWP);
                wmma::load_matrix_sync(b1, sWh + (jf * 16) * LDWP + colp + 16, LDWP);
                wmma::mma_sync(acc0, aF, b0, acc0);
                wmma::mma_sync(acc1, aF, b1, acc1);
            }
            wmma::store_matrix_sync(sEpi + colp,      acc0, LDE, wmma::mem_row_major);
            wmma::store_matrix_sync(sEpi + colp + 16, acc1, LDE, wmma::mem_row_major);
        }
        __syncthreads();

        // ---- gates (tanh.approx-based) ----
        const float* eb = sEpi + b * LDE;
        #pragma unroll
        for (int i = 0; i < 4; ++i) {
            int k = (i >> 1) * 64 + k0 + (i & 1);
            float r = sig_a(xr[i] + eb[k]       + sBhh[k]);
            float z = sig_a(xz[i] + eb[128 + k] + sBhh[128 + k]);
            float n = tanha(xn[i] + r * (eb[256 + k] + sBhh[256 + k]));
            h[i] = (1.f - z) * n + z * h[i];
        }

        // ---- writeback ----
        const size_t row = (size_t)(gb0 + b) * SEQ + tt;
        __half2 p0 = __floats2half2_rn(h[0], h[1]);
        __half2 p1 = __floats2half2_rn(h[2], h[3]);
        *(__half2*)&sH[b * LDH + k0]      = p0;
        *(__half2*)&sH[b * LDH + 64 + k0] = p1;
        if (LAYER == 0) {
            *(__half2*)&hout[row * H2 + dir * HID + k0]      = p0;
            *(__half2*)&hout[row * H2 + dir * HID + 64 + k0] = p1;
        } else {
            float p = fmaf(h[0], wf[0], fmaf(h[1], wf[1], fmaf(h[2], wf[2], h[3] * wf[3])));
            gpart[((size_t)dir * BL + row) * 32 + lane] = p;
        }
        __syncthreads();
    }
}

// ---------------- final head: out = sigmoid(sum(partF)+sum(partB)+bf) ----------------
__global__ __launch_bounds__(256) void final2(
    const float* __restrict__ part, const float* __restrict__ bf,
    float* __restrict__ out)
{
    size_t i = (size_t)blockIdx.x * 256 + threadIdx.x;
    const float4* p0 = (const float4*)(part + i * 32);
    const float4* p1 = (const float4*)(part + (size_t)BL * 32 + i * 32);
    float s = 0.f;
    #pragma unroll
    for (int q = 0; q < 8; ++q) { float4 v = p0[q]; s += v.x + v.y + v.z + v.w; }
    #pragma unroll
    for (int q = 0; q < 8; ++q) { float4 v = p1[q]; s += v.x + v.y + v.z + v.w; }
    out[i] = 1.f / (1.f + __expf(-(s + bf[0])));
}

// ---------------- launch ----------------
extern "C" void kernel_launch(void* const* d_in, const int* in_sizes, int n_in,
                              void* d_out, int out_size)
{
    const float* received = (const float*)d_in[0];
    const float* W_lin    = (const float*)d_in[1];
    const float* b_lin    = (const float*)d_in[2];
    const float* Wih0f = (const float*)d_in[3],  *Whh0f = (const float*)d_in[4];
    const float* bih0f = (const float*)d_in[5],  *bhh0f = (const float*)d_in[6];
    const float* Wih0b = (const float*)d_in[7],  *Whh0b = (const float*)d_in[8];
    const float* bih0b = (const float*)d_in[9],  *bhh0b = (const float*)d_in[10];
    const float* Wih1f = (const float*)d_in[11], *Whh1f = (const float*)d_in[12];
    const float* bih1f = (const float*)d_in[13], *bhh1f = (const float*)d_in[14];
    const float* Wih1b = (const float*)d_in[15], *Whh1b = (const float*)d_in[16];
    const float* bih1b = (const float*)d_in[17], *bhh1b = (const float*)d_in[18];
    const float* Wf    = (const float*)d_in[19], *bf    = (const float*)d_in[20];
    float* out = (float*)d_out;

    float *code, *part;
    __half *h0h, *xg1h;
    cudaGetSymbolAddress((void**)&code,  g_code);
    cudaGetSymbolAddress((void**)&h0h,   g_h0h);
    cudaGetSymbolAddress((void**)&xg1h,  g_xg1h);
    cudaGetSymbolAddress((void**)&part,  g_part);

    cudaFuncSetAttribute(gru_tc<0>, cudaFuncAttributeMaxDynamicSharedMemorySize, (int)SMEM_GRUTC);
    cudaFuncSetAttribute(gru_tc<1>, cudaFuncAttributeMaxDynamicSharedMemorySize, (int)SMEM_GRUTC);
    cudaFuncSetAttribute(xgemm7, cudaFuncAttributeMaxDynamicSharedMemorySize, (int)SMEM_X7);

    // 1) dec_linear
    sgemm_nt<<<dim3(BATCH / 64, (NLIN + 63) / 64), 256>>>(
        received, W_lin, b_lin, code, BATCH, NLIN, NLIN);

    // 2) layer-0 bidirectional GRU -> fp16 h0
    gru_tc<0><<<dim3(BATCH / TB, 2), 512, SMEM_GRUTC>>>(
        code, nullptr, Wih0f, Wih0b, Whh0f, Whh0b, bih0f, bih0b, bhh0f, bhh0b,
        nullptr, nullptr, h0h);

    // 3) layer-1 input projections (single-term fp16, fp16 output)
    xgemm7<<<dim3(6, 200), 512, SMEM_X7>>>(
        h0h, Wih1f, Wih1b, bih1f, bih1b, xg1h);

    // 4) layer-1 bidirectional GRU with fused head partials
    gru_tc<1><<<dim3(BATCH / TB, 2), 512, SMEM_GRUTC>>>(
        nullptr, xg1h, nullptr, nullptr, Whh1f, Whh1b, bih1f, bih1b, bhh1f, bhh1b,
        Wf, part, nullptr);

    // 5) output head reduction + sigmoid
    final2<<<BL / 256, 256>>>(part, bf, out);
}